// round 3
// baseline (speedup 1.0000x reference)
#include <cuda_runtime.h>
#include <math.h>
#include <stddef.h>

// ---------------- problem constants ----------------
#define BB   64
#define WW   128
#define CC   20
#define DD   256
#define NTOK (BB*WW)          // 8192 tokens
#define NPOS (NTOK*CC)        // 163840 char positions
#define HH   512
#define NBLK 128              // persistent blocks in recurrent kernel

// ---------------- device scratch (static, no allocations) ----------------
__device__ float g_X[(size_t)NTOK*22*DD];      // padded char embeddings (8192,22,256)
__device__ float g_cat[(size_t)NPOS*512];      // [bi|tri] features (163840,512)
__device__ float g_score[NPOS];
__device__ float g_wemb[(size_t)NTOK*512];
__device__ float g_feats[(size_t)NTOK*512];
__device__ float g_xg[(size_t)NTOK*4096];      // LSTM input gates, both dirs
__device__ float g_h0[(size_t)NTOK*1024];
__device__ float g_h1[(size_t)NTOK*1024];
__device__ float g_hbuf[2*2*64*512];           // [buf][dir][b][u]
__device__ float g_pe[20*256];
__device__ float g_Wcomb[512*768];             // combined conv weights
__device__ float g_bcomb[512];
__device__ float g_WaT[512*512];
__device__ float g_W1T[256*512];
__device__ unsigned int g_bar[16];

// safe transcendental helpers (stable even under --use_fast_math)
__device__ __forceinline__ float sigf(float x) { return 1.f / (1.f + expf(-x)); }
__device__ __forceinline__ float tanh_f(float x) {
    float e = expf(-2.f * fabsf(x));
    float r = (1.f - e) / (1.f + e);
    return x >= 0.f ? r : -r;
}

// ---------------- prep kernels ----------------
__global__ void prep_pe_k() {
    int idx = blockIdx.x * 256 + threadIdx.x;
    if (idx >= 20 * 256) return;
    int t = idx >> 8, j = idx & 255;
    int m2 = j & ~1;
    float div = expf(-(float)m2 * (logf(10000.f) / 256.f));
    float ang = (float)t * div;
    g_pe[idx] = (j & 1) ? cosf(ang) : sinf(ang);
}

__global__ void prep_wcomb_k(const float* __restrict__ wbi, const float* __restrict__ wtri,
                             const float* __restrict__ bbi, const float* __restrict__ btri) {
    int idx = blockIdx.x * 256 + threadIdx.x;  // 512*768 exact
    int o = idx / 768, r = idx % 768;
    int kk = r >> 8, i = r & 255;
    float v;
    if (o < 256) v = (kk < 2) ? wbi[(o * 256 + i) * 2 + kk] : 0.f;
    else         v = wtri[((o - 256) * 256 + i) * 3 + kk];
    g_Wcomb[idx] = v;
    if (idx < 512) g_bcomb[idx] = (idx < 256) ? bbi[idx] : btri[idx - 256];
}

__global__ void prep_wat_k(const float* __restrict__ Wa) {
    int idx = blockIdx.x * 256 + threadIdx.x;  // 512*512 exact
    int e = idx >> 9, d = idx & 511;
    g_WaT[idx] = Wa[d * 512 + e];
}

__global__ void prep_w1t_k(const float* __restrict__ W1) {
    int idx = blockIdx.x * 256 + threadIdx.x;  // 256*512 exact
    int j = idx >> 9, d = idx & 511;
    g_W1T[idx] = W1[d * 256 + j];
}

__global__ void gather_x_k(const int* __restrict__ src, const float* __restrict__ tab) {
    size_t idx = (size_t)blockIdx.x * 256 + threadIdx.x;  // 8192*22*256 exact
    int d = (int)(idx & 255);
    size_t row = idx >> 8;
    int t = (int)(row % 22);
    size_t n = row / 22;
    float v = 0.f;
    if (t < 20) {
        int ch = src[n * 20 + t];
        v = tab[(size_t)ch * 256 + d];
    }
    g_X[idx] = v;
}

// ---------------- generic 128x128x8 SGEMM body: C = A(M,K) * B(N,K)^T + bias ----------------
__device__ __forceinline__ void sgemm_body(
    const float* __restrict__ A, const float* __restrict__ B,
    float* __restrict__ C, const float* __restrict__ bias,
    int K, int ldc)
{
    __shared__ float As[8][128];
    __shared__ float Bs[8][128];
    int tid = threadIdx.x, tx = tid & 15, ty = tid >> 4;
    int m0 = blockIdx.y * 128, n0 = blockIdx.x * 128;
    int lr = tid >> 1, lc = (tid & 1) * 4;
    const float* Ab = A + (size_t)(m0 + lr) * K + lc;
    const float* Bb = B + (size_t)(n0 + lr) * K + lc;
    float acc[8][8];
#pragma unroll
    for (int i = 0; i < 8; i++)
#pragma unroll
        for (int j = 0; j < 8; j++) acc[i][j] = 0.f;
    for (int k0 = 0; k0 < K; k0 += 8) {
        float4 av = *(const float4*)(Ab + k0);
        float4 bv = *(const float4*)(Bb + k0);
        __syncthreads();
        As[lc + 0][lr] = av.x; As[lc + 1][lr] = av.y; As[lc + 2][lr] = av.z; As[lc + 3][lr] = av.w;
        Bs[lc + 0][lr] = bv.x; Bs[lc + 1][lr] = bv.y; Bs[lc + 2][lr] = bv.z; Bs[lc + 3][lr] = bv.w;
        __syncthreads();
#pragma unroll
        for (int kk = 0; kk < 8; kk++) {
            float a[8], b[8];
#pragma unroll
            for (int i = 0; i < 8; i++) a[i] = As[kk][ty + 16 * i];
#pragma unroll
            for (int j = 0; j < 8; j++) b[j] = Bs[kk][tx + 16 * j];
#pragma unroll
            for (int i = 0; i < 8; i++)
#pragma unroll
                for (int j = 0; j < 8; j++) acc[i][j] += a[i] * b[j];
        }
    }
#pragma unroll
    for (int j = 0; j < 8; j++) {
        int n = n0 + tx + 16 * j;
        float bj = bias ? bias[n] : 0.f;
#pragma unroll
        for (int i = 0; i < 8; i++) {
            int m = m0 + ty + 16 * i;
            C[(size_t)m * ldc + n] = acc[i][j] + bj;
        }
    }
}

// thin wrappers binding device globals
__global__ void __launch_bounds__(256) gemm_w1_k() {
    sgemm_body(g_wemb, g_W1T, g_feats, nullptr, 512, 512);
}
__global__ void __launch_bounds__(256) gemm_xg0_k(const float* __restrict__ wih0, const float* __restrict__ b0) {
    sgemm_body(g_feats, wih0, g_xg, b0, 512, 4096);
}
__global__ void __launch_bounds__(256) gemm_xg1_k(const float* __restrict__ wih1, const float* __restrict__ b1) {
    sgemm_body(g_h0, wih1, g_xg, b1, 1024, 4096);
}

// ---------------- conv-as-GEMM: cat = X_windows * Wcomb^T + bcomb + pe ----------------
__global__ void __launch_bounds__(256) sgemm_conv_k() {
    __shared__ float As[8][128];
    __shared__ float Bs[8][128];
    int tid = threadIdx.x, tx = tid & 15, ty = tid >> 4;
    int m0 = blockIdx.y * 128, n0 = blockIdx.x * 128;
    int lr = tid >> 1, lc = (tid & 1) * 4;
    int p = m0 + lr;
    int nn = p / 20, tt = p % 20;
    const float* Ab = g_X + (size_t)nn * 5632 + tt * 256 + lc;   // 768-wide window
    const float* Bb = g_Wcomb + (size_t)(n0 + lr) * 768 + lc;
    float acc[8][8];
#pragma unroll
    for (int i = 0; i < 8; i++)
#pragma unroll
        for (int j = 0; j < 8; j++) acc[i][j] = 0.f;
    for (int k0 = 0; k0 < 768; k0 += 8) {
        float4 av = *(const float4*)(Ab + k0);
        float4 bv = *(const float4*)(Bb + k0);
        __syncthreads();
        As[lc + 0][lr] = av.x; As[lc + 1][lr] = av.y; As[lc + 2][lr] = av.z; As[lc + 3][lr] = av.w;
        Bs[lc + 0][lr] = bv.x; Bs[lc + 1][lr] = bv.y; Bs[lc + 2][lr] = bv.z; Bs[lc + 3][lr] = bv.w;
        __syncthreads();
#pragma unroll
        for (int kk = 0; kk < 8; kk++) {
            float a[8], b[8];
#pragma unroll
            for (int i = 0; i < 8; i++) a[i] = As[kk][ty + 16 * i];
#pragma unroll
            for (int j = 0; j < 8; j++) b[j] = Bs[kk][tx + 16 * j];
#pragma unroll
            for (int i = 0; i < 8; i++)
#pragma unroll
                for (int j = 0; j < 8; j++) acc[i][j] += a[i] * b[j];
        }
    }
#pragma unroll
    for (int i = 0; i < 8; i++) {
        int m = m0 + ty + 16 * i;
        int t = m % 20;
#pragma unroll
        for (int j = 0; j < 8; j++) {
            int n = n0 + tx + 16 * j;
            g_cat[(size_t)m * 512 + n] = acc[i][j] + g_bcomb[n] + g_pe[t * 256 + (n & 255)];
        }
    }
}

// ---------------- fused attention score: score[p] = sum_e tanh(cat@Wa + ba)[e] * ua[e] ----------------
__global__ void __launch_bounds__(256) attn_score_k(const float* __restrict__ ba, const float* __restrict__ ua) {
    __shared__ float As[8][128];
    __shared__ float Bs[8][128];
    __shared__ float red[128 * 16];
    int tid = threadIdx.x, tx = tid & 15, ty = tid >> 4;
    int m0 = blockIdx.x * 128;
    int lr = tid >> 1, lc = (tid & 1) * 4;
    const float* Ab = g_cat + (size_t)(m0 + lr) * 512 + lc;
    float rs[8];
#pragma unroll
    for (int i = 0; i < 8; i++) rs[i] = 0.f;

    for (int nc = 0; nc < 4; nc++) {
        int n0 = nc * 128;
        const float* Bb = g_WaT + (size_t)(n0 + lr) * 512 + lc;
        float acc[8][8];
#pragma unroll
        for (int i = 0; i < 8; i++)
#pragma unroll
            for (int j = 0; j < 8; j++) acc[i][j] = 0.f;
        for (int k0 = 0; k0 < 512; k0 += 8) {
            float4 av = *(const float4*)(Ab + k0);
            float4 bv = *(const float4*)(Bb + k0);
            __syncthreads();
            As[lc + 0][lr] = av.x; As[lc + 1][lr] = av.y; As[lc + 2][lr] = av.z; As[lc + 3][lr] = av.w;
            Bs[lc + 0][lr] = bv.x; Bs[lc + 1][lr] = bv.y; Bs[lc + 2][lr] = bv.z; Bs[lc + 3][lr] = bv.w;
            __syncthreads();
#pragma unroll
            for (int kk = 0; kk < 8; kk++) {
                float a[8], b[8];
#pragma unroll
                for (int i = 0; i < 8; i++) a[i] = As[kk][ty + 16 * i];
#pragma unroll
                for (int j = 0; j < 8; j++) b[j] = Bs[kk][tx + 16 * j];
#pragma unroll
                for (int i = 0; i < 8; i++)
#pragma unroll
                    for (int j = 0; j < 8; j++) acc[i][j] += a[i] * b[j];
            }
        }
#pragma unroll
        for (int i = 0; i < 8; i++) {
#pragma unroll
            for (int j = 0; j < 8; j++) {
                int n = n0 + tx + 16 * j;
                rs[i] += tanh_f(acc[i][j] + ba[n]) * ua[n];
            }
        }
        __syncthreads();  // protect As/Bs before next chunk reload
    }
#pragma unroll
    for (int i = 0; i < 8; i++) red[(ty + 16 * i) * 16 + tx] = rs[i];
    __syncthreads();
    if (tid < 128) {
        float s = 0.f;
#pragma unroll
        for (int w = 0; w < 16; w++) s += red[tid * 16 + w];
        g_score[m0 + tid] = s;
    }
}

// ---------------- softmax over 20 chars + weighted pool -> word embeddings ----------------
__global__ void softmax_wemb_k() {
    __shared__ float a[20];
    int n = blockIdx.x, tid = threadIdx.x;
    if (tid == 0) {
        float sc[20]; float mx = -1e30f;
        for (int c = 0; c < 20; c++) { sc[c] = g_score[n * 20 + c]; mx = fmaxf(mx, sc[c]); }
        float sum = 0.f;
        for (int c = 0; c < 20; c++) { sc[c] = expf(sc[c] - mx); sum += sc[c]; }
        float inv = 1.f / sum;
        for (int c = 0; c < 20; c++) a[c] = sc[c] * inv;
    }
    __syncthreads();
    const float* base = g_cat + (size_t)n * 20 * 512;
    for (int d = tid; d < 512; d += 128) {
        float s = 0.f;
#pragma unroll
        for (int c = 0; c < 20; c++) s += base[c * 512 + d] * a[c];
        g_wemb[(size_t)n * 512 + d] = s;
    }
}

__global__ void gather_word_k(const int* __restrict__ word_src, const float* __restrict__ tab) {
    int idx = blockIdx.x * 256 + threadIdx.x;  // 8192*256 exact
    int n = idx >> 8, j = idx & 255;
    g_feats[(size_t)n * 512 + 256 + j] = tab[(size_t)word_src[n] * 256 + j];
}

// ---------------- persistent BiLSTM layer ----------------
// 128 blocks = 2 dirs x 64 u-chunks(8 u each). whh chunk (32 rows x 512) in smem,
// h staged per step via __ldcg, c in registers, device-wide counter barrier.
#define LSTM_SMEM ((32*520 + 64*520)*4)

__global__ void __launch_bounds__(256) lstm_layer_k(const float* __restrict__ whh, int which) {
    extern __shared__ float sh[];
    float* whh_s = sh;             // [32][520]
    float* h_s   = sh + 32 * 520;  // [64][520]
    int tid = threadIdx.x;
    int bd = blockIdx.x;
    int dir = bd >> 6;
    int uc = bd & 63;
    int u0 = uc * 8;
    const float* whhd = whh + (size_t)dir * 2048 * 512;
    for (int idx = tid; idx < 32 * 512; idx += 256) {
        int row = idx >> 9, k = idx & 511;
        int grow = (row >> 3) * 512 + u0 + (row & 7);
        whh_s[row * 520 + k] = whhd[(size_t)grow * 512 + k];
    }
    int ul = tid & 7;
    int bp = tid >> 3;  // 0..31
    float c0 = 0.f, c1 = 0.f;
    float* out = which ? g_h1 : g_h0;
    const int u = u0 + ul;
    const float* w0p = &whh_s[(0 * 8 + ul) * 520];
    const float* w1p = &whh_s[(1 * 8 + ul) * 520];
    const float* w2p = &whh_s[(2 * 8 + ul) * 520];
    const float* w3p = &whh_s[(3 * 8 + ul) * 520];
    const float* hap = &h_s[bp * 520];
    const float* hbp = &h_s[(bp + 32) * 520];

    for (int s = 0; s < 128; s++) {
        const float* hp = g_hbuf + ((size_t)((s & 1) * 2 + dir)) * 64 * 512;
        for (int idx = tid; idx < 64 * 512; idx += 256) {
            int b = idx >> 9, k = idx & 511;
            h_s[b * 520 + k] = __ldcg(hp + idx);
        }
        __syncthreads();

        float a00 = 0.f, a01 = 0.f, a10 = 0.f, a11 = 0.f;
        float a20 = 0.f, a21 = 0.f, a30 = 0.f, a31 = 0.f;
#pragma unroll 4
        for (int k = 0; k < 512; k++) {
            float ha = hap[k], hb = hbp[k];
            float w0 = w0p[k], w1 = w1p[k], w2 = w2p[k], w3 = w3p[k];
            a00 += w0 * ha; a01 += w0 * hb;
            a10 += w1 * ha; a11 += w1 * hb;
            a20 += w2 * ha; a21 += w2 * hb;
            a30 += w3 * ha; a31 += w3 * hb;
        }
        int t = dir ? (127 - s) : s;
        size_t nbuf = ((size_t)(((s & 1) ^ 1) * 2 + dir)) * 64 * 512;
        {
            size_t base = ((size_t)(bp * 128 + t)) * 4096 + (size_t)dir * 2048;
            float gi = a00 + g_xg[base + u];
            float gf = a10 + g_xg[base + 512 + u];
            float gg = a20 + g_xg[base + 1024 + u];
            float go = a30 + g_xg[base + 1536 + u];
            c0 = sigf(gf) * c0 + sigf(gi) * tanh_f(gg);
            float h = sigf(go) * tanh_f(c0);
            g_hbuf[nbuf + bp * 512 + u] = h;
            out[((size_t)(bp * 128 + t)) * 1024 + dir * 512 + u] = h;
        }
        {
            int b = bp + 32;
            size_t base = ((size_t)(b * 128 + t)) * 4096 + (size_t)dir * 2048;
            float gi = a01 + g_xg[base + u];
            float gf = a11 + g_xg[base + 512 + u];
            float gg = a21 + g_xg[base + 1024 + u];
            float go = a31 + g_xg[base + 1536 + u];
            c1 = sigf(gf) * c1 + sigf(gi) * tanh_f(gg);
            float h = sigf(go) * tanh_f(c1);
            g_hbuf[nbuf + b * 512 + u] = h;
            out[((size_t)(b * 128 + t)) * 1024 + dir * 512 + u] = h;
        }
        __threadfence();
        __syncthreads();
        if (tid == 0) {
            atomicAdd(&g_bar[0], 1u);
            unsigned target = (unsigned)NBLK * (unsigned)(s + 1);
            while (atomicAdd(&g_bar[0], 0u) < target) { }
        }
        __syncthreads();
    }
}

__global__ void lstm_reset_k() {
    int idx = blockIdx.x * 256 + threadIdx.x;  // 131072 exact
    g_hbuf[idx] = 0.f;
    if (idx < 16) g_bar[idx] = 0u;
}

// ---------------- mean pool + output projection ----------------
__global__ void pool_out_k(const float* __restrict__ Wout, float* __restrict__ out) {
    __shared__ float pooled[1024];
    __shared__ float red[256 * 4];
    int b = blockIdx.x, tid = threadIdx.x;
    for (int u = tid; u < 1024; u += 256) {
        float s = 0.f;
        for (int t = 0; t < 128; t++) s += g_h1[((size_t)(b * 128 + t)) * 1024 + u];
        pooled[u] = s * (1.f / 128.f);
    }
    __syncthreads();
    float loc[4] = {0.f, 0.f, 0.f, 0.f};
    for (int u = tid; u < 1024; u += 256) {
        float p = pooled[u];
#pragma unroll
        for (int o = 0; o < 4; o++) loc[o] += p * Wout[u * 4 + o];
    }
#pragma unroll
    for (int o = 0; o < 4; o++) red[tid * 4 + o] = loc[o];
    __syncthreads();
    if (tid < 4) {
        float s = 0.f;
        for (int i = 0; i < 256; i++) s += red[i * 4 + tid];
        out[b * 4 + tid] = s;
    }
}

// ---------------- launch ----------------
extern "C" void kernel_launch(void* const* d_in, const int* in_sizes, int n_in,
                              void* d_out, int out_size) {
    const int*   src        = (const int*)  d_in[0];
    const int*   word_src   = (const int*)  d_in[1];
    const float* char_table = (const float*)d_in[2];
    const float* word_table = (const float*)d_in[3];
    const float* w_bi  = (const float*)d_in[4];
    const float* b_bi  = (const float*)d_in[5];
    const float* w_tri = (const float*)d_in[6];
    const float* b_tri = (const float*)d_in[7];
    const float* Wa    = (const float*)d_in[8];
    const float* ba    = (const float*)d_in[9];
    const float* ua    = (const float*)d_in[10];
    const float* W1    = (const float*)d_in[11];
    const float* wih0  = (const float*)d_in[12];
    const float* whh0  = (const float*)d_in[13];
    const float* b0    = (const float*)d_in[14];
    const float* wih1  = (const float*)d_in[15];
    const float* whh1  = (const float*)d_in[16];
    const float* b1    = (const float*)d_in[17];
    const float* Wout  = (const float*)d_in[18];
    float* out = (float*)d_out;
    (void)in_sizes; (void)n_in; (void)out_size;

    cudaFuncSetAttribute(lstm_layer_k, cudaFuncAttributeMaxDynamicSharedMemorySize, LSTM_SMEM);

    // prep
    prep_pe_k<<<20, 256>>>();
    prep_wcomb_k<<<1536, 256>>>(w_bi, w_tri, b_bi, b_tri);
    prep_wat_k<<<1024, 256>>>(Wa);
    prep_w1t_k<<<512, 256>>>(W1);
    gather_x_k<<<8192 * 22, 256>>>(src, char_table);

    // char conv + PE
    { dim3 g(4, 1280); sgemm_conv_k<<<g, 256>>>(); }
    // fused attention score
    attn_score_k<<<1280, 256>>>(ba, ua);
    // softmax + weighted pool
    softmax_wemb_k<<<8192, 128>>>();
    // feats = [wemb @ W1 | word_table[word_src]]
    { dim3 g(2, 64); gemm_w1_k<<<g, 256>>>(); }
    gather_word_k<<<8192, 256>>>(word_src, word_table);

    // layer 0
    { dim3 g(32, 64); gemm_xg0_k<<<g, 256>>>(wih0, b0); }
    lstm_reset_k<<<512, 256>>>();
    lstm_layer_k<<<NBLK, 256, LSTM_SMEM>>>(whh0, 0);

    // layer 1
    { dim3 g(32, 64); gemm_xg1_k<<<g, 256>>>(wih1, b1); }
    lstm_reset_k<<<512, 256>>>();
    lstm_layer_k<<<NBLK, 256, LSTM_SMEM>>>(whh1, 1);

    // pool + out
    pool_out_k<<<64, 256>>>(Wout, out);
}

// round 4
// speedup vs baseline: 1.1824x; 1.1824x over previous
#include <cuda_runtime.h>
#include <math.h>
#include <stddef.h>

// ---------------- problem constants ----------------
#define BB   64
#define WW   128
#define CC   20
#define DD   256
#define NTOK (BB*WW)          // 8192 tokens
#define NPOS (NTOK*CC)        // 163840 char positions
#define HH   512
#define NBLK 128              // persistent blocks in recurrent kernel

// ---------------- device scratch (static, no allocations) ----------------
__device__ float g_X[(size_t)NTOK*22*DD];      // padded char embeddings (8192,22,256)
__device__ float g_cat[(size_t)NPOS*512];      // [bi|tri] features (163840,512)
__device__ float g_score[NPOS];
__device__ float g_wemb[(size_t)NTOK*512];
__device__ float g_feats[(size_t)NTOK*512];
__device__ float g_xg[(size_t)NTOK*4096];      // LSTM input gates, both dirs
__device__ float g_h0[(size_t)NTOK*1024];
__device__ float g_h1[(size_t)NTOK*1024];
__device__ float g_hbuf[2*2*64*512];           // [buf][dir][b][u]
__device__ float g_pe[20*256];
__device__ float g_Wcomb[512*768];             // combined conv weights
__device__ float g_bcomb[512];
__device__ float g_WaT[512*512];
__device__ float g_W1T[256*512];
__device__ unsigned int g_bar[16];

// safe transcendental helpers (stable even under --use_fast_math)
__device__ __forceinline__ float sigf(float x) { return 1.f / (1.f + expf(-x)); }
__device__ __forceinline__ float tanh_f(float x) {
    float e = expf(-2.f * fabsf(x));
    float r = (1.f - e) / (1.f + e);
    return x >= 0.f ? r : -r;
}

// ---------------- tf32 helpers ----------------
__device__ __forceinline__ void split_tf32(float x, unsigned& hi, unsigned& lo) {
    unsigned h; asm("cvt.rna.tf32.f32 %0, %1;" : "=r"(h) : "f"(x));
    float r = x - __uint_as_float(h);
    unsigned l; asm("cvt.rna.tf32.f32 %0, %1;" : "=r"(l) : "f"(r));
    hi = h; lo = l;
}
__device__ __forceinline__ void mma8(float* c, const unsigned* a, const unsigned* b) {
    asm volatile("mma.sync.aligned.m16n8k8.row.col.f32.tf32.tf32.f32 "
        "{%0,%1,%2,%3}, {%4,%5,%6,%7}, {%8,%9}, {%0,%1,%2,%3};"
        : "+f"(c[0]), "+f"(c[1]), "+f"(c[2]), "+f"(c[3])
        : "r"(a[0]), "r"(a[1]), "r"(a[2]), "r"(a[3]), "r"(b[0]), "r"(b[1]));
}

// smem tile: [128 rows][16 k] padded to stride 20 (conflict-free frag loads)
#define TS 20

// fragment load (a: 4 regs, rows g/g+8, k t4/t4+4)
__device__ __forceinline__ void ldfragA(unsigned* a, const unsigned* S, int rbase, int kb) {
    a[0] = S[rbase * TS + kb];
    a[1] = S[(rbase + 8) * TS + kb];
    a[2] = S[rbase * TS + kb + 4];
    a[3] = S[(rbase + 8) * TS + kb + 4];
}
__device__ __forceinline__ void ldfragB(unsigned* b, const unsigned* S, int cbase, int kb) {
    b[0] = S[cbase * TS + kb];
    b[1] = S[cbase * TS + kb + 4];
}

// 3xTF32 mma over one k-tile (2 kk-steps of 8)
#define MMA_TILE_COMPUTE(AsHi, AsLo, BsHi, BsLo, acc, wm, wn, g, t4)            \
    _Pragma("unroll")                                                           \
    for (int kk = 0; kk < 2; kk++) {                                            \
        int kb = kk * 8 + t4;                                                   \
        unsigned ah[4][4], al[4][4], bh[4][2], bl[4][2];                        \
        _Pragma("unroll")                                                       \
        for (int mi = 0; mi < 4; mi++) {                                        \
            int rb = (wm) * 64 + mi * 16 + (g);                                 \
            ldfragA(ah[mi], AsHi, rb, kb);                                      \
            ldfragA(al[mi], AsLo, rb, kb);                                      \
        }                                                                       \
        _Pragma("unroll")                                                       \
        for (int ni = 0; ni < 4; ni++) {                                        \
            int cb = (wn) * 32 + ni * 8 + (g);                                  \
            ldfragB(bh[ni], BsHi, cb, kb);                                      \
            ldfragB(bl[ni], BsLo, cb, kb);                                      \
        }                                                                       \
        _Pragma("unroll")                                                       \
        for (int mi = 0; mi < 4; mi++)                                          \
            _Pragma("unroll")                                                   \
            for (int ni = 0; ni < 4; ni++) {                                    \
                mma8(acc[mi][ni], ah[mi], bh[ni]);                              \
                mma8(acc[mi][ni], ah[mi], bl[ni]);                              \
                mma8(acc[mi][ni], al[mi], bh[ni]);                              \
            }                                                                   \
    }

#define STS_SPLIT(Hi, Lo, off, v)                                               \
    {                                                                           \
        unsigned h0,l0,h1,l1,h2,l2,h3,l3;                                       \
        split_tf32((v).x, h0, l0); split_tf32((v).y, h1, l1);                    \
        split_tf32((v).z, h2, l2); split_tf32((v).w, h3, l3);                    \
        Hi[(off)+0]=h0; Hi[(off)+1]=h1; Hi[(off)+2]=h2; Hi[(off)+3]=h3;          \
        Lo[(off)+0]=l0; Lo[(off)+1]=l1; Lo[(off)+2]=l2; Lo[(off)+3]=l3;          \
    }

// ---------------- prep kernels ----------------
__global__ void prep_pe_k() {
    int idx = blockIdx.x * 256 + threadIdx.x;
    if (idx >= 20 * 256) return;
    int t = idx >> 8, j = idx & 255;
    int m2 = j & ~1;
    float div = expf(-(float)m2 * (logf(10000.f) / 256.f));
    float ang = (float)t * div;
    g_pe[idx] = (j & 1) ? cosf(ang) : sinf(ang);
}

__global__ void prep_wcomb_k(const float* __restrict__ wbi, const float* __restrict__ wtri,
                             const float* __restrict__ bbi, const float* __restrict__ btri) {
    int idx = blockIdx.x * 256 + threadIdx.x;  // 512*768 exact
    int o = idx / 768, r = idx % 768;
    int kk = r >> 8, i = r & 255;
    float v;
    if (o < 256) v = (kk < 2) ? wbi[(o * 256 + i) * 2 + kk] : 0.f;
    else         v = wtri[((o - 256) * 256 + i) * 3 + kk];
    g_Wcomb[idx] = v;
    if (idx < 512) g_bcomb[idx] = (idx < 256) ? bbi[idx] : btri[idx - 256];
}

__global__ void prep_wat_k(const float* __restrict__ Wa) {
    int idx = blockIdx.x * 256 + threadIdx.x;  // 512*512 exact
    int e = idx >> 9, d = idx & 511;
    g_WaT[idx] = Wa[d * 512 + e];
}

__global__ void prep_w1t_k(const float* __restrict__ W1) {
    int idx = blockIdx.x * 256 + threadIdx.x;  // 256*512 exact
    int j = idx >> 9, d = idx & 511;
    g_W1T[idx] = W1[d * 256 + j];
}

__global__ void gather_x_k(const int* __restrict__ src, const float* __restrict__ tab) {
    size_t idx = (size_t)blockIdx.x * 256 + threadIdx.x;  // 8192*22*256 exact
    int d = (int)(idx & 255);
    size_t row = idx >> 8;
    int t = (int)(row % 22);
    size_t n = row / 22;
    float v = 0.f;
    if (t < 20) {
        int ch = src[n * 20 + t];
        v = tab[(size_t)ch * 256 + d];
    }
    g_X[idx] = v;
}

// ---------------- generic 3xTF32 mma GEMM: C = A(M,K) * B(N,K)^T + bias ----------------
__global__ void __launch_bounds__(256) mma_gemm_k(
    const float* __restrict__ A, const float* __restrict__ B,
    float* __restrict__ C, const float* __restrict__ bias, int K, int ldc)
{
    __shared__ unsigned AsHi[128 * TS], AsLo[128 * TS];
    __shared__ unsigned BsHi[128 * TS], BsLo[128 * TS];
    int tid = threadIdx.x;
    int wid = tid >> 5, lane = tid & 31;
    int wm = wid & 1, wn = wid >> 1;
    int g = lane >> 2, t4 = lane & 3;
    int m0 = blockIdx.y * 128, n0 = blockIdx.x * 128;

    const float* aptr[2]; const float* bptr[2];
    int soff[2];
#pragma unroll
    for (int i = 0; i < 2; i++) {
        int idx = tid + i * 256;
        int r = idx >> 2, kc = (idx & 3) * 4;
        soff[i] = r * TS + kc;
        aptr[i] = A + (size_t)(m0 + r) * K + kc;
        bptr[i] = B + (size_t)(n0 + r) * K + kc;
    }
    float acc[4][4][4];
#pragma unroll
    for (int mi = 0; mi < 4; mi++)
#pragma unroll
        for (int ni = 0; ni < 4; ni++)
#pragma unroll
            for (int j = 0; j < 4; j++) acc[mi][ni][j] = 0.f;

    float4 pa[2], pb[2];
#pragma unroll
    for (int i = 0; i < 2; i++) { pa[i] = *(const float4*)aptr[i]; pb[i] = *(const float4*)bptr[i]; }

    for (int k0 = 0; k0 < K; k0 += 16) {
        __syncthreads();
#pragma unroll
        for (int i = 0; i < 2; i++) {
            STS_SPLIT(AsHi, AsLo, soff[i], pa[i]);
            STS_SPLIT(BsHi, BsLo, soff[i], pb[i]);
        }
        __syncthreads();
        if (k0 + 16 < K) {
#pragma unroll
            for (int i = 0; i < 2; i++) {
                pa[i] = *(const float4*)(aptr[i] + k0 + 16);
                pb[i] = *(const float4*)(bptr[i] + k0 + 16);
            }
        }
        MMA_TILE_COMPUTE(AsHi, AsLo, BsHi, BsLo, acc, wm, wn, g, t4)
    }

#pragma unroll
    for (int mi = 0; mi < 4; mi++) {
        int mlo = m0 + wm * 64 + mi * 16 + g;
#pragma unroll
        for (int ni = 0; ni < 4; ni++) {
            int n = n0 + wn * 32 + ni * 8 + t4 * 2;
            float b0v = bias ? bias[n] : 0.f;
            float b1v = bias ? bias[n + 1] : 0.f;
            C[(size_t)mlo * ldc + n]           = acc[mi][ni][0] + b0v;
            C[(size_t)mlo * ldc + n + 1]       = acc[mi][ni][1] + b1v;
            C[(size_t)(mlo + 8) * ldc + n]     = acc[mi][ni][2] + b0v;
            C[(size_t)(mlo + 8) * ldc + n + 1] = acc[mi][ni][3] + b1v;
        }
    }
}

// ---------------- conv-as-GEMM (window view of g_X), epilogue += bcomb + pe ----------------
__global__ void __launch_bounds__(256) mma_conv_k() {
    __shared__ unsigned AsHi[128 * TS], AsLo[128 * TS];
    __shared__ unsigned BsHi[128 * TS], BsLo[128 * TS];
    int tid = threadIdx.x;
    int wid = tid >> 5, lane = tid & 31;
    int wm = wid & 1, wn = wid >> 1;
    int g = lane >> 2, t4 = lane & 3;
    int m0 = blockIdx.y * 128, n0 = blockIdx.x * 128;

    const float* aptr[2]; const float* bptr[2];
    int soff[2];
#pragma unroll
    for (int i = 0; i < 2; i++) {
        int idx = tid + i * 256;
        int r = idx >> 2, kc = (idx & 3) * 4;
        soff[i] = r * TS + kc;
        int p = m0 + r;
        int nn = p / 20, tt = p % 20;
        aptr[i] = g_X + (size_t)nn * 5632 + tt * 256 + kc;   // contiguous 768-wide window
        bptr[i] = g_Wcomb + (size_t)(n0 + r) * 768 + kc;
    }
    float acc[4][4][4];
#pragma unroll
    for (int mi = 0; mi < 4; mi++)
#pragma unroll
        for (int ni = 0; ni < 4; ni++)
#pragma unroll
            for (int j = 0; j < 4; j++) acc[mi][ni][j] = 0.f;

    float4 pa[2], pb[2];
#pragma unroll
    for (int i = 0; i < 2; i++) { pa[i] = *(const float4*)aptr[i]; pb[i] = *(const float4*)bptr[i]; }

    for (int k0 = 0; k0 < 768; k0 += 16) {
        __syncthreads();
#pragma unroll
        for (int i = 0; i < 2; i++) {
            STS_SPLIT(AsHi, AsLo, soff[i], pa[i]);
            STS_SPLIT(BsHi, BsLo, soff[i], pb[i]);
        }
        __syncthreads();
        if (k0 + 16 < 768) {
#pragma unroll
            for (int i = 0; i < 2; i++) {
                pa[i] = *(const float4*)(aptr[i] + k0 + 16);
                pb[i] = *(const float4*)(bptr[i] + k0 + 16);
            }
        }
        MMA_TILE_COMPUTE(AsHi, AsLo, BsHi, BsLo, acc, wm, wn, g, t4)
    }

#pragma unroll
    for (int mi = 0; mi < 4; mi++) {
#pragma unroll
        for (int half = 0; half < 2; half++) {
            int m = m0 + wm * 64 + mi * 16 + g + half * 8;
            int t = m % 20;
#pragma unroll
            for (int ni = 0; ni < 4; ni++) {
                int n = n0 + wn * 32 + ni * 8 + t4 * 2;
                float v0 = acc[mi][ni][half * 2 + 0] + g_bcomb[n]     + g_pe[t * 256 + (n & 255)];
                float v1 = acc[mi][ni][half * 2 + 1] + g_bcomb[n + 1] + g_pe[t * 256 + ((n + 1) & 255)];
                g_cat[(size_t)m * 512 + n]     = v0;
                g_cat[(size_t)m * 512 + n + 1] = v1;
            }
        }
    }
}

// ---------------- fused attention score: score[p] = sum_e tanh(cat@Wa + ba)[e]*ua[e] ----------------
__global__ void __launch_bounds__(256) mma_attn_k(const float* __restrict__ ba, const float* __restrict__ ua) {
    __shared__ unsigned AsHi[128 * TS], AsLo[128 * TS];
    __shared__ unsigned BsHi[128 * TS], BsLo[128 * TS];
    __shared__ float sBa[512], sUa[512];
    __shared__ float red[128 * 4];
    int tid = threadIdx.x;
    int wid = tid >> 5, lane = tid & 31;
    int wm = wid & 1, wn = wid >> 1;
    int g = lane >> 2, t4 = lane & 3;
    int m0 = blockIdx.x * 128;

#pragma unroll
    for (int i = 0; i < 2; i++) {
        int j = tid + i * 256;
        sBa[j] = ba[j]; sUa[j] = ua[j];
    }

    const float* aptr[2];
    int soff[2], brow[2], bkc[2];
#pragma unroll
    for (int i = 0; i < 2; i++) {
        int idx = tid + i * 256;
        int r = idx >> 2, kc = (idx & 3) * 4;
        soff[i] = r * TS + kc;
        brow[i] = r; bkc[i] = kc;
        aptr[i] = g_cat + (size_t)(m0 + r) * 512 + kc;
    }

    float rs[4][2];
#pragma unroll
    for (int mi = 0; mi < 4; mi++) { rs[mi][0] = 0.f; rs[mi][1] = 0.f; }

    for (int nc = 0; nc < 4; nc++) {
        int n0c = nc * 128;
        const float* bptr[2];
#pragma unroll
        for (int i = 0; i < 2; i++)
            bptr[i] = g_WaT + (size_t)(n0c + brow[i]) * 512 + bkc[i];

        float acc[4][4][4];
#pragma unroll
        for (int mi = 0; mi < 4; mi++)
#pragma unroll
            for (int ni = 0; ni < 4; ni++)
#pragma unroll
                for (int j = 0; j < 4; j++) acc[mi][ni][j] = 0.f;

        float4 pa[2], pb[2];
#pragma unroll
        for (int i = 0; i < 2; i++) { pa[i] = *(const float4*)aptr[i]; pb[i] = *(const float4*)bptr[i]; }

        for (int k0 = 0; k0 < 512; k0 += 16) {
            __syncthreads();
#pragma unroll
            for (int i = 0; i < 2; i++) {
                STS_SPLIT(AsHi, AsLo, soff[i], pa[i]);
                STS_SPLIT(BsHi, BsLo, soff[i], pb[i]);
            }
            __syncthreads();
            if (k0 + 16 < 512) {
#pragma unroll
                for (int i = 0; i < 2; i++) {
                    pa[i] = *(const float4*)(aptr[i] + k0 + 16);
                    pb[i] = *(const float4*)(bptr[i] + k0 + 16);
                }
            }
            MMA_TILE_COMPUTE(AsHi, AsLo, BsHi, BsLo, acc, wm, wn, g, t4)
        }

        // epilogue: rs += tanh(acc + ba)*ua over this 128-col chunk
#pragma unroll
        for (int mi = 0; mi < 4; mi++)
#pragma unroll
            for (int ni = 0; ni < 4; ni++)
#pragma unroll
                for (int cj = 0; cj < 4; cj++) {
                    int col = n0c + wn * 32 + ni * 8 + t4 * 2 + (cj & 1);
                    rs[mi][cj >> 1] += tanh_f(acc[mi][ni][cj] + sBa[col]) * sUa[col];
                }
    }

    // reduce: 4 lanes (t4) share a row, then 4 n-warps
#pragma unroll
    for (int mi = 0; mi < 4; mi++)
#pragma unroll
        for (int h = 0; h < 2; h++) {
            float v = rs[mi][h];
            v += __shfl_xor_sync(0xffffffffu, v, 1);
            v += __shfl_xor_sync(0xffffffffu, v, 2);
            if (t4 == 0) {
                int r = wm * 64 + mi * 16 + g + h * 8;
                red[r * 4 + wn] = v;
            }
        }
    __syncthreads();
    if (tid < 128) {
        float s = red[tid * 4] + red[tid * 4 + 1] + red[tid * 4 + 2] + red[tid * 4 + 3];
        g_score[m0 + tid] = s;
    }
}

// ---------------- softmax over 20 chars + weighted pool ----------------
__global__ void softmax_wemb_k() {
    __shared__ float a[20];
    int n = blockIdx.x, tid = threadIdx.x;
    if (tid == 0) {
        float sc[20]; float mx = -1e30f;
        for (int c = 0; c < 20; c++) { sc[c] = g_score[n * 20 + c]; mx = fmaxf(mx, sc[c]); }
        float sum = 0.f;
        for (int c = 0; c < 20; c++) { sc[c] = expf(sc[c] - mx); sum += sc[c]; }
        float inv = 1.f / sum;
        for (int c = 0; c < 20; c++) a[c] = sc[c] * inv;
    }
    __syncthreads();
    const float* base = g_cat + (size_t)n * 20 * 512;
    for (int d = tid; d < 512; d += 128) {
        float s = 0.f;
#pragma unroll
        for (int c = 0; c < 20; c++) s += base[c * 512 + d] * a[c];
        g_wemb[(size_t)n * 512 + d] = s;
    }
}

__global__ void gather_word_k(const int* __restrict__ word_src, const float* __restrict__ tab) {
    int idx = blockIdx.x * 256 + threadIdx.x;  // 8192*256 exact
    int n = idx >> 8, j = idx & 255;
    g_feats[(size_t)n * 512 + 256 + j] = tab[(size_t)word_src[n] * 256 + j];
}

// ---------------- persistent BiLSTM layer ----------------
#define LSTM_SMEM ((32*520 + 64*520)*4)

__global__ void __launch_bounds__(256) lstm_layer_k(const float* __restrict__ whh, int which) {
    extern __shared__ float sh[];
    float* whh_s = sh;             // [32][520]
    float* h_s   = sh + 32 * 520;  // [64][520]
    int tid = threadIdx.x;
    int bd = blockIdx.x;
    int dir = bd >> 6;
    int uc = bd & 63;
    int u0 = uc * 8;
    const float* whhd = whh + (size_t)dir * 2048 * 512;
    for (int idx = tid; idx < 32 * 512; idx += 256) {
        int row = idx >> 9, k = idx & 511;
        int grow = (row >> 3) * 512 + u0 + (row & 7);
        whh_s[row * 520 + k] = whhd[(size_t)grow * 512 + k];
    }
    int ul = tid & 7;
    int bp = tid >> 3;  // 0..31
    float c0 = 0.f, c1 = 0.f;
    float* out = which ? g_h1 : g_h0;
    const int u = u0 + ul;
    const float* w0p = &whh_s[(0 * 8 + ul) * 520];
    const float* w1p = &whh_s[(1 * 8 + ul) * 520];
    const float* w2p = &whh_s[(2 * 8 + ul) * 520];
    const float* w3p = &whh_s[(3 * 8 + ul) * 520];
    const float* hap = &h_s[bp * 520];
    const float* hbp = &h_s[(bp + 32) * 520];

    for (int s = 0; s < 128; s++) {
        const float* hp = g_hbuf + ((size_t)((s & 1) * 2 + dir)) * 64 * 512;
        for (int idx = tid; idx < 64 * 512; idx += 256) {
            int b = idx >> 9, k = idx & 511;
            h_s[b * 520 + k] = __ldcg(hp + idx);
        }
        __syncthreads();

        float a00 = 0.f, a01 = 0.f, a10 = 0.f, a11 = 0.f;
        float a20 = 0.f, a21 = 0.f, a30 = 0.f, a31 = 0.f;
#pragma unroll 4
        for (int k = 0; k < 512; k++) {
            float ha = hap[k], hb = hbp[k];
            float w0 = w0p[k], w1 = w1p[k], w2 = w2p[k], w3 = w3p[k];
            a00 += w0 * ha; a01 += w0 * hb;
            a10 += w1 * ha; a11 += w1 * hb;
            a20 += w2 * ha; a21 += w2 * hb;
            a30 += w3 * ha; a31 += w3 * hb;
        }
        int t = dir ? (127 - s) : s;
        size_t nbuf = ((size_t)(((s & 1) ^ 1) * 2 + dir)) * 64 * 512;
        {
            size_t base = ((size_t)(bp * 128 + t)) * 4096 + (size_t)dir * 2048;
            float gi = a00 + g_xg[base + u];
            float gf = a10 + g_xg[base + 512 + u];
            float gg = a20 + g_xg[base + 1024 + u];
            float go = a30 + g_xg[base + 1536 + u];
            c0 = sigf(gf) * c0 + sigf(gi) * tanh_f(gg);
            float h = sigf(go) * tanh_f(c0);
            g_hbuf[nbuf + bp * 512 + u] = h;
            out[((size_t)(bp * 128 + t)) * 1024 + dir * 512 + u] = h;
        }
        {
            int b = bp + 32;
            size_t base = ((size_t)(b * 128 + t)) * 4096 + (size_t)dir * 2048;
            float gi = a01 + g_xg[base + u];
            float gf = a11 + g_xg[base + 512 + u];
            float gg = a21 + g_xg[base + 1024 + u];
            float go = a31 + g_xg[base + 1536 + u];
            c1 = sigf(gf) * c1 + sigf(gi) * tanh_f(gg);
            float h = sigf(go) * tanh_f(c1);
            g_hbuf[nbuf + b * 512 + u] = h;
            out[((size_t)(b * 128 + t)) * 1024 + dir * 512 + u] = h;
        }
        __threadfence();
        __syncthreads();
        if (tid == 0) {
            atomicAdd(&g_bar[0], 1u);
            unsigned target = (unsigned)NBLK * (unsigned)(s + 1);
            while (atomicAdd(&g_bar[0], 0u) < target) { }
        }
        __syncthreads();
    }
}

__global__ void lstm_reset_k() {
    int idx = blockIdx.x * 256 + threadIdx.x;  // 131072 exact
    g_hbuf[idx] = 0.f;
    if (idx < 16) g_bar[idx] = 0u;
}

// ---------------- mean pool + output projection ----------------
__global__ void pool_out_k(const float* __restrict__ Wout, float* __restrict__ out) {
    __shared__ float pooled[1024];
    __shared__ float red[256 * 4];
    int b = blockIdx.x, tid = threadIdx.x;
    for (int u = tid; u < 1024; u += 256) {
        float s = 0.f;
        for (int t = 0; t < 128; t++) s += g_h1[((size_t)(b * 128 + t)) * 1024 + u];
        pooled[u] = s * (1.f / 128.f);
    }
    __syncthreads();
    float loc[4] = {0.f, 0.f, 0.f, 0.f};
    for (int u = tid; u < 1024; u += 256) {
        float p = pooled[u];
#pragma unroll
        for (int o = 0; o < 4; o++) loc[o] += p * Wout[u * 4 + o];
    }
#pragma unroll
    for (int o = 0; o < 4; o++) red[tid * 4 + o] = loc[o];
    __syncthreads();
    if (tid < 4) {
        float s = 0.f;
        for (int i = 0; i < 256; i++) s += red[i * 4 + tid];
        out[b * 4 + tid] = s;
    }
}

// ---------------- launch ----------------
extern "C" void kernel_launch(void* const* d_in, const int* in_sizes, int n_in,
                              void* d_out, int out_size) {
    const int*   src        = (const int*)  d_in[0];
    const int*   word_src   = (const int*)  d_in[1];
    const float* char_table = (const float*)d_in[2];
    const float* word_table = (const float*)d_in[3];
    const float* w_bi  = (const float*)d_in[4];
    const float* b_bi  = (const float*)d_in[5];
    const float* w_tri = (const float*)d_in[6];
    const float* b_tri = (const float*)d_in[7];
    const float* Wa    = (const float*)d_in[8];
    const float* ba    = (const float*)d_in[9];
    const float* ua    = (const float*)d_in[10];
    const float* W1    = (const float*)d_in[11];
    const float* wih0  = (const float*)d_in[12];
    const float* whh0  = (const float*)d_in[13];
    const float* b0    = (const float*)d_in[14];
    const float* wih1  = (const float*)d_in[15];
    const float* whh1  = (const float*)d_in[16];
    const float* b1    = (const float*)d_in[17];
    const float* Wout  = (const float*)d_in[18];
    float* out = (float*)d_out;
    (void)in_sizes; (void)n_in; (void)out_size;

    cudaFuncSetAttribute(lstm_layer_k, cudaFuncAttributeMaxDynamicSharedMemorySize, LSTM_SMEM);

    // resolve device-global addresses for passing as plain pointers
    float *pX, *pCat, *pWemb, *pFeats, *pXg, *pH0, *pH1, *pWcomb, *pWaT, *pW1T;
    cudaGetSymbolAddress((void**)&pX, g_X);
    cudaGetSymbolAddress((void**)&pCat, g_cat);
    cudaGetSymbolAddress((void**)&pWemb, g_wemb);
    cudaGetSymbolAddress((void**)&pFeats, g_feats);
    cudaGetSymbolAddress((void**)&pXg, g_xg);
    cudaGetSymbolAddress((void**)&pH0, g_h0);
    cudaGetSymbolAddress((void**)&pH1, g_h1);
    cudaGetSymbolAddress((void**)&pWcomb, g_Wcomb);
    cudaGetSymbolAddress((void**)&pWaT, g_WaT);
    cudaGetSymbolAddress((void**)&pW1T, g_W1T);

    // prep
    prep_pe_k<<<20, 256>>>();
    prep_wcomb_k<<<1536, 256>>>(w_bi, w_tri, b_bi, b_tri);
    prep_wat_k<<<1024, 256>>>(Wa);
    prep_w1t_k<<<512, 256>>>(W1);
    gather_x_k<<<8192 * 22, 256>>>(src, char_table);

    // char conv + PE (tensor cores)
    { dim3 gr(4, 1280); mma_conv_k<<<gr, 256>>>(); }
    // fused attention score (tensor cores)
    mma_attn_k<<<1280, 256>>>(ba, ua);
    // softmax + weighted pool
    softmax_wemb_k<<<8192, 128>>>();
    // feats = [wemb @ W1 | word_table[word_src]]
    { dim3 gr(2, 64); mma_gemm_k<<<gr, 256>>>(pWemb, pW1T, pFeats, nullptr, 512, 512); }
    gather_word_k<<<8192, 256>>>(word_src, word_table);

    // layer 0
    { dim3 gr(32, 64); mma_gemm_k<<<gr, 256>>>(pFeats, wih0, pXg, b0, 512, 4096); }
    lstm_reset_k<<<512, 256>>>();
    lstm_layer_k<<<NBLK, 256, LSTM_SMEM>>>(whh0, 0);

    // layer 1
    { dim3 gr(32, 64); mma_gemm_k<<<gr, 256>>>(pH0, wih1, pXg, b1, 1024, 4096); }
    lstm_reset_k<<<512, 256>>>();
    lstm_layer_k<<<NBLK, 256, LSTM_SMEM>>>(whh1, 1);

    // pool + out
    pool_out_k<<<64, 256>>>(Wout, out);
}

// round 9
// speedup vs baseline: 1.5115x; 1.2784x over previous
#include <cuda_runtime.h>
#include <cuda_bf16.h>
#include <math.h>
#include <stddef.h>
#include <stdint.h>

// ---------------- problem constants ----------------
#define BB   64
#define WW   128
#define CC   20
#define DD   256
#define NTOK (BB*WW)          // 8192
#define NPOS (NTOK*CC)        // 163840
#define NBLK 128

// ---------------- device scratch ----------------
__device__ __nv_bfloat16 g_Xhi[(size_t)NTOK*22*DD];
__device__ __nv_bfloat16 g_Xlo[(size_t)NTOK*22*DD];
__device__ __nv_bfloat16 g_cathi[(size_t)NPOS*512];
__device__ __nv_bfloat16 g_catlo[(size_t)NPOS*512];
__device__ __nv_bfloat16 g_wembhi[(size_t)NTOK*512];
__device__ __nv_bfloat16 g_wemblo[(size_t)NTOK*512];
__device__ __nv_bfloat16 g_featshi[(size_t)NTOK*512];
__device__ __nv_bfloat16 g_featslo[(size_t)NTOK*512];
__device__ __nv_bfloat16 g_h0hi[(size_t)NTOK*1024];
__device__ __nv_bfloat16 g_h0lo[(size_t)NTOK*1024];
__device__ __nv_bfloat16 g_Wcombhi[512*768];
__device__ __nv_bfloat16 g_Wcomblo[512*768];
__device__ __nv_bfloat16 g_WaThi[512*512];
__device__ __nv_bfloat16 g_WaTlo[512*512];
__device__ __nv_bfloat16 g_W1Thi[256*512];
__device__ __nv_bfloat16 g_W1Tlo[256*512];
__device__ __nv_bfloat16 g_wih0hi[4096*512];
__device__ __nv_bfloat16 g_wih0lo[4096*512];
__device__ __nv_bfloat16 g_wih1hi[(size_t)4096*1024];
__device__ __nv_bfloat16 g_wih1lo[(size_t)4096*1024];
__device__ float g_xg[(size_t)NTOK*4096];
__device__ float g_h1[(size_t)NTOK*1024];
__device__ float g_hbuf[2*2*64*512];
__device__ float g_score[NPOS];
__device__ float g_pe[20*256];
__device__ float g_bcomb[512];
__device__ unsigned int g_bar[16];

// ---------------- math helpers ----------------
__device__ __forceinline__ float sigf(float x) { return 1.f / (1.f + expf(-x)); }
__device__ __forceinline__ float tanh_f(float x) {
    float e = expf(-2.f * fabsf(x));
    float r = (1.f - e) / (1.f + e);
    return x >= 0.f ? r : -r;
}
__device__ __forceinline__ void split_bf(float v, __nv_bfloat16& hi, __nv_bfloat16& lo) {
    hi = __float2bfloat16(v);
    lo = __float2bfloat16(v - __bfloat162float(hi));
}

// ---------------- mma.sync bf16 helpers ----------------
__device__ __forceinline__ uint32_t smem_u32(const void* p) {
    uint32_t a;
    asm("{ .reg .u64 t; cvta.to.shared.u64 t, %1; cvt.u32.u64 %0, t; }" : "=r"(a) : "l"(p));
    return a;
}
__device__ __forceinline__ void ldsm_x4(uint32_t* r, uint32_t addr) {
    asm volatile("ldmatrix.sync.aligned.m8n8.x4.shared.b16 {%0,%1,%2,%3}, [%4];"
        : "=r"(r[0]), "=r"(r[1]), "=r"(r[2]), "=r"(r[3]) : "r"(addr));
}
__device__ __forceinline__ void ldsm_x2(uint32_t* r, uint32_t addr) {
    asm volatile("ldmatrix.sync.aligned.m8n8.x2.shared.b16 {%0,%1}, [%2];"
        : "=r"(r[0]), "=r"(r[1]) : "r"(addr));
}
__device__ __forceinline__ void mma_bf16(float* c, const uint32_t* a, const uint32_t* b) {
    asm volatile("mma.sync.aligned.m16n8k16.row.col.f32.bf16.bf16.f32 "
        "{%0,%1,%2,%3}, {%4,%5,%6,%7}, {%8,%9}, {%0,%1,%2,%3};"
        : "+f"(c[0]), "+f"(c[1]), "+f"(c[2]), "+f"(c[3])
        : "r"(a[0]), "r"(a[1]), "r"(a[2]), "r"(a[3]), "r"(b[0]), "r"(b[1]));
}
#define CP_ASYNC16(dst, src) \
    asm volatile("cp.async.cg.shared.global [%0], [%1], 16;" :: "r"(dst), "l"(src))
#define CP_COMMIT() asm volatile("cp.async.commit_group;" ::: "memory")
#define CP_WAIT1()  asm volatile("cp.async.wait_group 1;" ::: "memory")
#define CP_WAIT0()  asm volatile("cp.async.wait_group 0;" ::: "memory")

// smem layout: 80B-padded rows (conflict-free ldmatrix), double-buffered A+B
#define ROWB   80
#define TILEB  (128*ROWB)          // 10240
#define BUFB   (2*TILEB)           // 20480 per buffer (A then B)
#define SM_RED 40960
#define SM_WIN 43008
#define SMEM_DYN (SM_WIN + 512)

// ---------------- prep kernels ----------------
__global__ void prep_pe_k() {
    int idx = blockIdx.x * 256 + threadIdx.x;
    if (idx >= 20 * 256) return;
    int t = idx >> 8, j = idx & 255;
    int m2 = j & ~1;
    float div = expf(-(float)m2 * (logf(10000.f) / 256.f));
    float ang = (float)t * div;
    g_pe[idx] = (j & 1) ? cosf(ang) : sinf(ang);
}

__global__ void prep_wcomb_k(const float* __restrict__ wbi, const float* __restrict__ wtri,
                             const float* __restrict__ bbi, const float* __restrict__ btri) {
    int idx = blockIdx.x * 256 + threadIdx.x;  // 512*768 exact
    int o = idx / 768, r = idx % 768;
    int kk = r >> 8, i = r & 255;
    float v;
    if (o < 256) v = (kk < 2) ? wbi[(o * 256 + i) * 2 + kk] : 0.f;
    else         v = wtri[((o - 256) * 256 + i) * 3 + kk];
    __nv_bfloat16 h, l; split_bf(v, h, l);
    g_Wcombhi[idx] = h; g_Wcomblo[idx] = l;
    if (idx < 512) g_bcomb[idx] = (idx < 256) ? bbi[idx] : btri[idx - 256];
}

__global__ void prep_wat_k(const float* __restrict__ Wa) {
    int idx = blockIdx.x * 256 + threadIdx.x;  // 512*512 exact
    int e = idx >> 9, d = idx & 511;
    __nv_bfloat16 h, l; split_bf(Wa[d * 512 + e], h, l);
    g_WaThi[idx] = h; g_WaTlo[idx] = l;
}

__global__ void prep_w1t_k(const float* __restrict__ W1) {
    int idx = blockIdx.x * 256 + threadIdx.x;  // 256*512 exact
    int j = idx >> 9, d = idx & 511;
    __nv_bfloat16 h, l; split_bf(W1[d * 256 + j], h, l);
    g_W1Thi[idx] = h; g_W1Tlo[idx] = l;
}

__global__ void split2_k(const float* __restrict__ in, __nv_bfloat16* __restrict__ hi,
                         __nv_bfloat16* __restrict__ lo, int n) {
    int i = blockIdx.x * 256 + threadIdx.x;
    if (i >= n) return;
    __nv_bfloat16 h, l; split_bf(in[i], h, l);
    hi[i] = h; lo[i] = l;
}

__global__ void gather_x_k(const int* __restrict__ src, const float* __restrict__ tab) {
    size_t idx = (size_t)blockIdx.x * 256 + threadIdx.x;  // 8192*22*256 exact
    int d = (int)(idx & 255);
    size_t row = idx >> 8;
    int t = (int)(row % 22);
    size_t n = row / 22;
    float v = 0.f;
    if (t < 20) v = tab[(size_t)src[n * 20 + t] * 256 + d];
    __nv_bfloat16 h, l; split_bf(v, h, l);
    g_Xhi[idx] = h; g_Xlo[idx] = l;
}

__global__ void gather_word_k(const int* __restrict__ word_src, const float* __restrict__ tab) {
    int idx = blockIdx.x * 256 + threadIdx.x;  // 8192*256 exact
    int n = idx >> 8, j = idx & 255;
    __nv_bfloat16 h, l; split_bf(tab[(size_t)word_src[n] * 256 + j], h, l);
    g_featshi[(size_t)n * 512 + 256 + j] = h;
    g_featslo[(size_t)n * 512 + 256 + j] = l;
}

// ---------------- bf16 mma.sync GEMM: C(128,128 tiles) = A * B^T, 3-segment split ----
// MODE: 0 = fp32 C + bias (xg), 1 = conv (bf16 cat + bcomb + pe), 2 = attn (tanh.ua reduce),
//       3 = w1 (bf16 feats, no bias)
template<int MODE>
__global__ void __launch_bounds__(256) mma_gemm_k(
    const __nv_bfloat16* __restrict__ Ahi, const __nv_bfloat16* __restrict__ Alo,
    const __nv_bfloat16* __restrict__ Bhi, const __nv_bfloat16* __restrict__ Blo,
    int K,
    float* __restrict__ Cf, const float* __restrict__ bias, int ldc,
    const float* __restrict__ ba, const float* __restrict__ ua)
{
    extern __shared__ char smem[];
    uint32_t sb = smem_u32(smem);
    int tid = threadIdx.x, wid = tid >> 5, lane = tid & 31;
    int wm = wid & 1, wn = wid >> 1;
    int g = lane >> 2, t4 = lane & 3;
    int m0 = (MODE == 2) ? blockIdx.x * 128 : blockIdx.y * 128;
    int n0 = (MODE == 2) ? 0 : blockIdx.x * 128;

    int* winb = (int*)(smem + SM_WIN);
    if (MODE == 1 && tid < 128) {
        int m = m0 + tid;
        winb[tid] = (m / 20) * 5632 + (m % 20) * 256;
    }
    __syncthreads();

    // loader indices: 256 threads x (2 A rows + 2 B rows), 4x 16B chunks per row of 32 bf16
    int lr = tid >> 2;          // 0..63
    int lc = tid & 3;           // chunk
    const int nChunk = K >> 5;  // k-tiles of 32
    const int NIT = 3 * nChunk;
    const int npass = (MODE == 2) ? 4 : 1;

    float rs[4][2];
#pragma unroll
    for (int mi = 0; mi < 4; mi++) { rs[mi][0] = 0.f; rs[mi][1] = 0.f; }

    for (int ps = 0; ps < npass; ps++) {
        int bRow0 = (MODE == 2) ? ps * 128 : n0;

        float acc[4][4][4];
#pragma unroll
        for (int mi = 0; mi < 4; mi++)
#pragma unroll
            for (int ni = 0; ni < 4; ni++)
#pragma unroll
                for (int j = 0; j < 4; j++) acc[mi][ni][j] = 0.f;

        // ---- issue helper (expanded inline twice) ----
#define ISSUE_TILE(IT, BUF)                                                          \
        {                                                                            \
            int seg_ = (IT) / nChunk;                                                \
            int kl_ = ((IT) - seg_ * nChunk) * 32;                                   \
            const __nv_bfloat16* As_ = (seg_ == 1) ? Alo : Ahi;                      \
            const __nv_bfloat16* Bs_ = (seg_ == 2) ? Blo : Bhi;                      \
            uint32_t ab_ = sb + (BUF) * BUFB;                                        \
            uint32_t bb_ = ab_ + TILEB;                                              \
            size_t ga0, ga1;                                                         \
            if (MODE == 1) {                                                         \
                ga0 = (size_t)winb[lr] + kl_ + lc * 8;                               \
                ga1 = (size_t)winb[lr + 64] + kl_ + lc * 8;                          \
            } else {                                                                 \
                ga0 = (size_t)(m0 + lr) * K + kl_ + lc * 8;                          \
                ga1 = (size_t)(m0 + lr + 64) * K + kl_ + lc * 8;                     \
            }                                                                        \
            CP_ASYNC16(ab_ + lr * ROWB + lc * 16, As_ + ga0);                        \
            CP_ASYNC16(ab_ + (lr + 64) * ROWB + lc * 16, As_ + ga1);                 \
            size_t gb0 = (size_t)(bRow0 + lr) * K + kl_ + lc * 8;                    \
            size_t gb1 = (size_t)(bRow0 + lr + 64) * K + kl_ + lc * 8;               \
            CP_ASYNC16(bb_ + lr * ROWB + lc * 16, Bs_ + gb0);                        \
            CP_ASYNC16(bb_ + (lr + 64) * ROWB + lc * 16, Bs_ + gb1);                 \
            CP_COMMIT();                                                             \
        }

        ISSUE_TILE(0, 0)
        for (int it = 0; it < NIT; it++) {
            if (it + 1 < NIT) { ISSUE_TILE(it + 1, (it + 1) & 1) CP_WAIT1(); }
            else CP_WAIT0();
            __syncthreads();
            {
                uint32_t ab = sb + (it & 1) * BUFB;
                uint32_t bb = ab + TILEB;
                uint32_t a_lane = ab + (uint32_t)(wm * 64 + (lane & 15)) * ROWB + (uint32_t)(lane >> 4) * 16;
                uint32_t b_lane = bb + (uint32_t)(wn * 32 + (lane & 7)) * ROWB + (uint32_t)((lane >> 3) & 1) * 16;
#pragma unroll
                for (int s = 0; s < 2; s++) {
                    uint32_t af[4][4], bf[4][2];
#pragma unroll
                    for (int mi = 0; mi < 4; mi++)
                        ldsm_x4(af[mi], a_lane + (uint32_t)(mi * 16 * ROWB) + (uint32_t)(s * 32));
#pragma unroll
                    for (int ni = 0; ni < 4; ni++)
                        ldsm_x2(bf[ni], b_lane + (uint32_t)(ni * 8 * ROWB) + (uint32_t)(s * 32));
#pragma unroll
                    for (int mi = 0; mi < 4; mi++)
#pragma unroll
                        for (int ni = 0; ni < 4; ni++)
                            mma_bf16(acc[mi][ni], af[mi], bf[ni]);
                }
            }
            __syncthreads();
        }
#undef ISSUE_TILE

        if (MODE == 2) {
            // rs += tanh(acc + ba)*ua over this 128-col pass
#pragma unroll
            for (int mi = 0; mi < 4; mi++)
#pragma unroll
                for (int ni = 0; ni < 4; ni++)
#pragma unroll
                    for (int cj = 0; cj < 4; cj++) {
                        int col = ps * 128 + wn * 32 + ni * 8 + t4 * 2 + (cj & 1);
                        rs[mi][cj >> 1] += tanh_f(acc[mi][ni][cj] + __ldg(ba + col)) * __ldg(ua + col);
                    }
        } else {
            // direct epilogue
#pragma unroll
            for (int mi = 0; mi < 4; mi++) {
#pragma unroll
                for (int half = 0; half < 2; half++) {
                    int m = m0 + wm * 64 + mi * 16 + g + half * 8;
#pragma unroll
                    for (int ni = 0; ni < 4; ni++) {
                        int n = n0 + wn * 32 + ni * 8 + t4 * 2;
                        float v0 = acc[mi][ni][half * 2 + 0];
                        float v1 = acc[mi][ni][half * 2 + 1];
                        if (MODE == 0) {
                            Cf[(size_t)m * ldc + n]     = v0 + __ldg(bias + n);
                            Cf[(size_t)m * ldc + n + 1] = v1 + __ldg(bias + n + 1);
                        } else if (MODE == 1) {
                            int t = m % 20;
                            float w0 = v0 + g_bcomb[n]     + g_pe[t * 256 + (n & 255)];
                            float w1 = v1 + g_bcomb[n + 1] + g_pe[t * 256 + ((n + 1) & 255)];
                            __nv_bfloat16 h, l;
                            split_bf(w0, h, l);
                            g_cathi[(size_t)m * 512 + n] = h; g_catlo[(size_t)m * 512 + n] = l;
                            split_bf(w1, h, l);
                            g_cathi[(size_t)m * 512 + n + 1] = h; g_catlo[(size_t)m * 512 + n + 1] = l;
                        } else {  // MODE 3
                            __nv_bfloat16 h, l;
                            split_bf(v0, h, l);
                            g_featshi[(size_t)m * 512 + n] = h; g_featslo[(size_t)m * 512 + n] = l;
                            split_bf(v1, h, l);
                            g_featshi[(size_t)m * 512 + n + 1] = h; g_featslo[(size_t)m * 512 + n + 1] = l;
                        }
                    }
                }
            }
        }
    }

    if (MODE == 2) {
        float* red = (float*)(smem + SM_RED);
#pragma unroll
        for (int mi = 0; mi < 4; mi++)
#pragma unroll
            for (int h = 0; h < 2; h++) {
                float v = rs[mi][h];
                v += __shfl_xor_sync(0xffffffffu, v, 1);
                v += __shfl_xor_sync(0xffffffffu, v, 2);
                if (t4 == 0) {
                    int r = wm * 64 + mi * 16 + g + h * 8;
                    red[r * 4 + wn] = v;
                }
            }
        __syncthreads();
        if (tid < 128) {
            float s = red[tid * 4] + red[tid * 4 + 1] + red[tid * 4 + 2] + red[tid * 4 + 3];
            g_score[m0 + tid] = s;
        }
    }
}

// ---------------- softmax over 20 chars + weighted pool (bf16-pair input) -------------
__global__ void softmax_wemb_k() {
    __shared__ float a[20];
    int n = blockIdx.x, tid = threadIdx.x;
    if (tid == 0) {
        float sc[20]; float mx = -1e30f;
        for (int c = 0; c < 20; c++) { sc[c] = g_score[n * 20 + c]; mx = fmaxf(mx, sc[c]); }
        float sum = 0.f;
        for (int c = 0; c < 20; c++) { sc[c] = expf(sc[c] - mx); sum += sc[c]; }
        float inv = 1.f / sum;
        for (int c = 0; c < 20; c++) a[c] = sc[c] * inv;
    }
    __syncthreads();
    size_t base = (size_t)n * 20 * 512;
    for (int d = tid; d < 512; d += 128) {
        float s = 0.f;
#pragma unroll
        for (int c = 0; c < 20; c++) {
            size_t i = base + (size_t)c * 512 + d;
            s += (__bfloat162float(g_cathi[i]) + __bfloat162float(g_catlo[i])) * a[c];
        }
        __nv_bfloat16 h, l; split_bf(s, h, l);
        g_wembhi[(size_t)n * 512 + d] = h;
        g_wemblo[(size_t)n * 512 + d] = l;
    }
}

// ---------------- persistent BiLSTM layer ----------------
#define LSTM_SMEM ((32*520 + 64*520)*4)

__global__ void __launch_bounds__(256) lstm_layer_k(const float* __restrict__ whh, int which) {
    extern __shared__ float sh[];
    float* whh_s = sh;             // [32][520]
    float* h_s   = sh + 32 * 520;  // [64][520]
    int tid = threadIdx.x;
    int bd = blockIdx.x;
    int dir = bd >> 6;
    int uc = bd & 63;
    int u0 = uc * 8;
    const float* whhd = whh + (size_t)dir * 2048 * 512;
    for (int idx = tid; idx < 32 * 512; idx += 256) {
        int row = idx >> 9, k = idx & 511;
        int grow = (row >> 3) * 512 + u0 + (row & 7);
        whh_s[row * 520 + k] = whhd[(size_t)grow * 512 + k];
    }
    int ul = tid & 7;
    int bp = tid >> 3;
    float c0 = 0.f, c1 = 0.f;
    const int u = u0 + ul;
    const float* w0p = &whh_s[(0 * 8 + ul) * 520];
    const float* w1p = &whh_s[(1 * 8 + ul) * 520];
    const float* w2p = &whh_s[(2 * 8 + ul) * 520];
    const float* w3p = &whh_s[(3 * 8 + ul) * 520];
    const float* hap = &h_s[bp * 520];
    const float* hbp = &h_s[(bp + 32) * 520];

    for (int s = 0; s < 128; s++) {
        const float* hp = g_hbuf + ((size_t)((s & 1) * 2 + dir)) * 64 * 512;
        for (int idx = tid; idx < 64 * 512; idx += 256) {
            int b = idx >> 9, k = idx & 511;
            h_s[b * 520 + k] = __ldcg(hp + idx);
        }
        __syncthreads();

        float a00 = 0.f, a01 = 0.f, a10 = 0.f, a11 = 0.f;
        float a20 = 0.f, a21 = 0.f, a30 = 0.f, a31 = 0.f;
#pragma unroll 4
        for (int k = 0; k < 512; k++) {
            float ha = hap[k], hb = hbp[k];
            float w0 = w0p[k], w1 = w1p[k], w2 = w2p[k], w3 = w3p[k];
            a00 += w0 * ha; a01 += w0 * hb;
            a10 += w1 * ha; a11 += w1 * hb;
            a20 += w2 * ha; a21 += w2 * hb;
            a30 += w3 * ha; a31 += w3 * hb;
        }
        int t = dir ? (127 - s) : s;
        size_t nbuf = ((size_t)(((s & 1) ^ 1) * 2 + dir)) * 64 * 512;
        {
            size_t base = ((size_t)(bp * 128 + t)) * 4096 + (size_t)dir * 2048;
            float gi = a00 + g_xg[base + u];
            float gf = a10 + g_xg[base + 512 + u];
            float gg = a20 + g_xg[base + 1024 + u];
            float go = a30 + g_xg[base + 1536 + u];
            c0 = sigf(gf) * c0 + sigf(gi) * tanh_f(gg);
            float h = sigf(go) * tanh_f(c0);
            g_hbuf[nbuf + bp * 512 + u] = h;
            size_t orow = ((size_t)(bp * 128 + t)) * 1024 + dir * 512 + u;
            if (which) g_h1[orow] = h;
            else { __nv_bfloat16 hh, ll; split_bf(h, hh, ll); g_h0hi[orow] = hh; g_h0lo[orow] = ll; }
        }
        {
            int b = bp + 32;
            size_t base = ((size_t)(b * 128 + t)) * 4096 + (size_t)dir * 2048;
            float gi = a01 + g_xg[base + u];
            float gf = a11 + g_xg[base + 512 + u];
            float gg = a21 + g_xg[base + 1024 + u];
            float go = a31 + g_xg[base + 1536 + u];
            c1 = sigf(gf) * c1 + sigf(gi) * tanh_f(gg);
            float h = sigf(go) * tanh_f(c1);
            g_hbuf[nbuf + b * 512 + u] = h;
            size_t orow = ((size_t)(b * 128 + t)) * 1024 + dir * 512 + u;
            if (which) g_h1[orow] = h;
            else { __nv_bfloat16 hh, ll; split_bf(h, hh, ll); g_h0hi[orow] = hh; g_h0lo[orow] = ll; }
        }
        __threadfence();
        __syncthreads();
        if (tid == 0) {
            atomicAdd(&g_bar[0], 1u);
            unsigned target = (unsigned)NBLK * (unsigned)(s + 1);
            while (atomicAdd(&g_bar[0], 0u) < target) { }
        }
        __syncthreads();
    }
}

__global__ void lstm_reset_k() {
    int idx = blockIdx.x * 256 + threadIdx.x;  // 131072 exact
    g_hbuf[idx] = 0.f;
    if (idx < 16) g_bar[idx] = 0u;
}

// ---------------- mean pool + output projection ----------------
__global__ void pool_out_k(const float* __restrict__ Wout, float* __restrict__ out) {
    __shared__ float pooled[1024];
    __shared__ float red[256 * 4];
    int b = blockIdx.x, tid = threadIdx.x;
    for (int u = tid; u < 1024; u += 256) {
        float s = 0.f;
        for (int t = 0; t < 128; t++) s += g_h1[((size_t)(b * 128 + t)) * 1024 + u];
        pooled[u] = s * (1.f / 128.f);
    }
    __syncthreads();
    float loc[4] = {0.f, 0.f, 0.f, 0.f};
    for (int u = tid; u < 1024; u += 256) {
        float p = pooled[u];
#pragma unroll
        for (int o = 0; o < 4; o++) loc[o] += p * Wout[u * 4 + o];
    }
#pragma unroll
    for (int o = 0; o < 4; o++) red[tid * 4 + o] = loc[o];
    __syncthreads();
    if (tid < 4) {
        float s = 0.f;
        for (int i = 0; i < 256; i++) s += red[i * 4 + tid];
        out[b * 4 + tid] = s;
    }
}

// ---------------- launch ----------------
extern "C" void kernel_launch(void* const* d_in, const int* in_sizes, int n_in,
                              void* d_out, int out_size) {
    const int*   src        = (const int*)  d_in[0];
    const int*   word_src   = (const int*)  d_in[1];
    const float* char_table = (const float*)d_in[2];
    const float* word_table = (const float*)d_in[3];
    const float* w_bi  = (const float*)d_in[4];
    const float* b_bi  = (const float*)d_in[5];
    const float* w_tri = (const float*)d_in[6];
    const float* b_tri = (const float*)d_in[7];
    const float* Wa    = (const float*)d_in[8];
    const float* ba    = (const float*)d_in[9];
    const float* ua    = (const float*)d_in[10];
    const float* W1    = (const float*)d_in[11];
    const float* wih0  = (const float*)d_in[12];
    const float* whh0  = (const float*)d_in[13];
    const float* b0    = (const float*)d_in[14];
    const float* wih1  = (const float*)d_in[15];
    const float* whh1  = (const float*)d_in[16];
    const float* b1    = (const float*)d_in[17];
    const float* Wout  = (const float*)d_in[18];
    float* out = (float*)d_out;
    (void)in_sizes; (void)n_in; (void)out_size;

    cudaFuncSetAttribute(lstm_layer_k, cudaFuncAttributeMaxDynamicSharedMemorySize, LSTM_SMEM);
    cudaFuncSetAttribute(mma_gemm_k<0>, cudaFuncAttributeMaxDynamicSharedMemorySize, SMEM_DYN);
    cudaFuncSetAttribute(mma_gemm_k<1>, cudaFuncAttributeMaxDynamicSharedMemorySize, SMEM_DYN);
    cudaFuncSetAttribute(mma_gemm_k<2>, cudaFuncAttributeMaxDynamicSharedMemorySize, SMEM_DYN);
    cudaFuncSetAttribute(mma_gemm_k<3>, cudaFuncAttributeMaxDynamicSharedMemorySize, SMEM_DYN);

    __nv_bfloat16 *pXhi, *pXlo, *pCathi, *pCatlo, *pWembhi, *pWemblo, *pFhi, *pFlo,
                  *pH0hi, *pH0lo, *pWchi, *pWclo, *pWahi, *pWalo, *pW1hi, *pW1lo,
                  *pWi0hi, *pWi0lo, *pWi1hi, *pWi1lo;
    float *pXg;
    cudaGetSymbolAddress((void**)&pXhi, g_Xhi);     cudaGetSymbolAddress((void**)&pXlo, g_Xlo);
    cudaGetSymbolAddress((void**)&pCathi, g_cathi); cudaGetSymbolAddress((void**)&pCatlo, g_catlo);
    cudaGetSymbolAddress((void**)&pWembhi, g_wembhi); cudaGetSymbolAddress((void**)&pWemblo, g_wemblo);
    cudaGetSymbolAddress((void**)&pFhi, g_featshi); cudaGetSymbolAddress((void**)&pFlo, g_featslo);
    cudaGetSymbolAddress((void**)&pH0hi, g_h0hi);   cudaGetSymbolAddress((void**)&pH0lo, g_h0lo);
    cudaGetSymbolAddress((void**)&pWchi, g_Wcombhi); cudaGetSymbolAddress((void**)&pWclo, g_Wcomblo);
    cudaGetSymbolAddress((void**)&pWahi, g_WaThi);  cudaGetSymbolAddress((void**)&pWalo, g_WaTlo);
    cudaGetSymbolAddress((void**)&pW1hi, g_W1Thi);  cudaGetSymbolAddress((void**)&pW1lo, g_W1Tlo);
    cudaGetSymbolAddress((void**)&pWi0hi, g_wih0hi); cudaGetSymbolAddress((void**)&pWi0lo, g_wih0lo);
    cudaGetSymbolAddress((void**)&pWi1hi, g_wih1hi); cudaGetSymbolAddress((void**)&pWi1lo, g_wih1lo);
    cudaGetSymbolAddress((void**)&pXg, g_xg);

    gather_x_k<<<8192 * 22, 256>>>(src, char_table);
    prep_wcomb_k<<<1536, 256>>>(w_bi, w_tri, b_bi, b_tri);
    prep_pe_k<<<20, 256>>>();
    { dim3 gr(4, 1280); mma_gemm_k<1><<<gr, 256, SMEM_DYN>>>(pXhi, pXlo, pWchi, pWclo,
        768, nullptr, nullptr, 0, nullptr, nullptr); }

    prep_wat_k<<<1024, 256>>>(Wa);
    mma_gemm_k<2><<<1280, 256, SMEM_DYN>>>(pCathi, pCatlo, pWahi, pWalo,
        512, nullptr, nullptr, 0, ba, ua);
    softmax_wemb_k<<<8192, 128>>>();

    prep_w1t_k<<<512, 256>>>(W1);
    { dim3 gr(2, 64); mma_gemm_k<3><<<gr, 256, SMEM_DYN>>>(pWembhi, pWemblo, pW1hi, pW1lo,
        512, nullptr, nullptr, 0, nullptr, nullptr); }
    gather_word_k<<<8192, 256>>>(word_src, word_table);

    // layer 0
    split2_k<<<8192, 256>>>(wih0, pWi0hi, pWi0lo, 4096 * 512);
    { dim3 gr(32, 64); mma_gemm_k<0><<<gr, 256, SMEM_DYN>>>(pFhi, pFlo, pWi0hi, pWi0lo,
        512, pXg, b0, 4096, nullptr, nullptr); }
    lstm_reset_k<<<512, 256>>>();
    lstm_layer_k<<<NBLK, 256, LSTM_SMEM>>>(whh0, 0);

    // layer 1
    split2_k<<<16384, 256>>>(wih1, pWi1hi, pWi1lo, 4096 * 1024);
    { dim3 gr(32, 64); mma_gemm_k<0><<<gr, 256, SMEM_DYN>>>(pH0hi, pH0lo, pWi1hi, pWi1lo,
        1024, pXg, b1, 4096, nullptr, nullptr); }
    lstm_reset_k<<<512, 256>>>();
    lstm_layer_k<<<NBLK, 256, LSTM_SMEM>>>(whh1, 1);

    pool_out_k<<<64, 256>>>(Wout, out);
}

// round 11
// speedup vs baseline: 1.8668x; 1.2350x over previous
#include <cuda_runtime.h>
#include <cuda_bf16.h>
#include <math.h>
#include <stddef.h>
#include <stdint.h>

// ---------------- problem constants ----------------
#define BB   64
#define WW   128
#define CC   20
#define DD   256
#define NTOK (BB*WW)          // 8192
#define NPOS (NTOK*CC)        // 163840
#define NBLK 128

// ---------------- device scratch ----------------
__device__ __nv_bfloat16 g_Xhi[(size_t)NTOK*22*DD];
__device__ __nv_bfloat16 g_Xlo[(size_t)NTOK*22*DD];
__device__ __nv_bfloat16 g_cathi[(size_t)NPOS*512];
__device__ __nv_bfloat16 g_catlo[(size_t)NPOS*512];
__device__ __nv_bfloat16 g_wembhi[(size_t)NTOK*512];
__device__ __nv_bfloat16 g_wemblo[(size_t)NTOK*512];
__device__ __nv_bfloat16 g_featshi[(size_t)NTOK*512];
__device__ __nv_bfloat16 g_featslo[(size_t)NTOK*512];
__device__ __nv_bfloat16 g_h0hi[(size_t)NTOK*1024];
__device__ __nv_bfloat16 g_h0lo[(size_t)NTOK*1024];
__device__ __nv_bfloat16 g_Wcombhi[512*768];
__device__ __nv_bfloat16 g_Wcomblo[512*768];
__device__ __nv_bfloat16 g_WaThi[512*512];
__device__ __nv_bfloat16 g_WaTlo[512*512];
__device__ __nv_bfloat16 g_W1Thi[256*512];
__device__ __nv_bfloat16 g_W1Tlo[256*512];
__device__ __nv_bfloat16 g_wih0hi[4096*512];
__device__ __nv_bfloat16 g_wih0lo[4096*512];
__device__ __nv_bfloat16 g_wih1hi[(size_t)4096*1024];
__device__ __nv_bfloat16 g_wih1lo[(size_t)4096*1024];
__device__ float g_xg[(size_t)NTOK*4096];
__device__ float g_h1[(size_t)NTOK*1024];
__device__ float g_hbuf[2*2*64*512];
__device__ float g_score[NPOS];
__device__ float g_pe[20*256];
__device__ float g_bcomb[512];
__device__ unsigned int g_bar[16];

// ---------------- math helpers ----------------
__device__ __forceinline__ float sigf(float x) { return 1.f / (1.f + expf(-x)); }
__device__ __forceinline__ float tanh_f(float x) {
    float e = expf(-2.f * fabsf(x));
    float r = (1.f - e) / (1.f + e);
    return x >= 0.f ? r : -r;
}
__device__ __forceinline__ void split_bf(float v, __nv_bfloat16& hi, __nv_bfloat16& lo) {
    hi = __float2bfloat16(v);
    lo = __float2bfloat16(v - __bfloat162float(hi));
}

// ---------------- packed f32x2 helpers (B300 FFMA2; family-safe sm_100+) ----------------
__device__ __forceinline__ void fma2(unsigned long long& c, unsigned long long a, unsigned long long b) {
    asm("fma.rn.f32x2 %0, %1, %2, %0;" : "+l"(c) : "l"(a), "l"(b));
}
__device__ __forceinline__ unsigned long long pack2(float x, float y) {
    unsigned long long r; asm("mov.b64 %0, {%1, %2};" : "=l"(r) : "f"(x), "f"(y)); return r;
}
__device__ __forceinline__ void unpack2(unsigned long long v, float& x, float& y) {
    asm("mov.b64 {%0, %1}, %2;" : "=f"(x), "=f"(y) : "l"(v));
}

// ---------------- mma.sync bf16 helpers ----------------
__device__ __forceinline__ uint32_t smem_u32(const void* p) {
    uint32_t a;
    asm("{ .reg .u64 t; cvta.to.shared.u64 t, %1; cvt.u32.u64 %0, t; }" : "=r"(a) : "l"(p));
    return a;
}
__device__ __forceinline__ void ldsm_x4(uint32_t* r, uint32_t addr) {
    asm volatile("ldmatrix.sync.aligned.m8n8.x4.shared.b16 {%0,%1,%2,%3}, [%4];"
        : "=r"(r[0]), "=r"(r[1]), "=r"(r[2]), "=r"(r[3]) : "r"(addr));
}
__device__ __forceinline__ void ldsm_x2(uint32_t* r, uint32_t addr) {
    asm volatile("ldmatrix.sync.aligned.m8n8.x2.shared.b16 {%0,%1}, [%2];"
        : "=r"(r[0]), "=r"(r[1]) : "r"(addr));
}
__device__ __forceinline__ void mma_bf16(float* c, const uint32_t* a, const uint32_t* b) {
    asm volatile("mma.sync.aligned.m16n8k16.row.col.f32.bf16.bf16.f32 "
        "{%0,%1,%2,%3}, {%4,%5,%6,%7}, {%8,%9}, {%0,%1,%2,%3};"
        : "+f"(c[0]), "+f"(c[1]), "+f"(c[2]), "+f"(c[3])
        : "r"(a[0]), "r"(a[1]), "r"(a[2]), "r"(a[3]), "r"(b[0]), "r"(b[1]));
}
#define CP_ASYNC16(dst, src) \
    asm volatile("cp.async.cg.shared.global [%0], [%1], 16;" :: "r"(dst), "l"(src))
#define CP_COMMIT() asm volatile("cp.async.commit_group;" ::: "memory")
#define CP_WAIT1()  asm volatile("cp.async.wait_group 1;" ::: "memory")
#define CP_WAIT0()  asm volatile("cp.async.wait_group 0;" ::: "memory")

// smem layout: 80B-padded rows (conflict-free ldmatrix), double-buffered A+B
#define ROWB   80
#define TILEB  (128*ROWB)          // 10240
#define BUFB   (2*TILEB)           // 20480 per buffer (A then B)
#define SM_RED 40960
#define SM_WIN 43008
#define SMEM_DYN (SM_WIN + 512)

// ---------------- prep kernels ----------------
__global__ void prep_pe_k() {
    int idx = blockIdx.x * 256 + threadIdx.x;
    if (idx >= 20 * 256) return;
    int t = idx >> 8, j = idx & 255;
    int m2 = j & ~1;
    float div = expf(-(float)m2 * (logf(10000.f) / 256.f));
    float ang = (float)t * div;
    g_pe[idx] = (j & 1) ? cosf(ang) : sinf(ang);
}

__global__ void prep_wcomb_k(const float* __restrict__ wbi, const float* __restrict__ wtri,
                             const float* __restrict__ bbi, const float* __restrict__ btri) {
    int idx = blockIdx.x * 256 + threadIdx.x;  // 512*768 exact
    int o = idx / 768, r = idx % 768;
    int kk = r >> 8, i = r & 255;
    float v;
    if (o < 256) v = (kk < 2) ? wbi[(o * 256 + i) * 2 + kk] : 0.f;
    else         v = wtri[((o - 256) * 256 + i) * 3 + kk];
    __nv_bfloat16 h, l; split_bf(v, h, l);
    g_Wcombhi[idx] = h; g_Wcomblo[idx] = l;
    if (idx < 512) g_bcomb[idx] = (idx < 256) ? bbi[idx] : btri[idx - 256];
}

__global__ void prep_wat_k(const float* __restrict__ Wa) {
    int idx = blockIdx.x * 256 + threadIdx.x;  // 512*512 exact
    int e = idx >> 9, d = idx & 511;
    __nv_bfloat16 h, l; split_bf(Wa[d * 512 + e], h, l);
    g_WaThi[idx] = h; g_WaTlo[idx] = l;
}

__global__ void prep_w1t_k(const float* __restrict__ W1) {
    int idx = blockIdx.x * 256 + threadIdx.x;  // 256*512 exact
    int j = idx >> 9, d = idx & 511;
    __nv_bfloat16 h, l; split_bf(W1[d * 256 + j], h, l);
    g_W1Thi[idx] = h; g_W1Tlo[idx] = l;
}

__global__ void split2_k(const float* __restrict__ in, __nv_bfloat16* __restrict__ hi,
                         __nv_bfloat16* __restrict__ lo, int n) {
    int i = blockIdx.x * 256 + threadIdx.x;
    if (i >= n) return;
    __nv_bfloat16 h, l; split_bf(in[i], h, l);
    hi[i] = h; lo[i] = l;
}

__global__ void gather_x_k(const int* __restrict__ src, const float* __restrict__ tab) {
    size_t idx = (size_t)blockIdx.x * 256 + threadIdx.x;  // 8192*22*256 exact
    int d = (int)(idx & 255);
    size_t row = idx >> 8;
    int t = (int)(row % 22);
    size_t n = row / 22;
    float v = 0.f;
    if (t < 20) v = tab[(size_t)src[n * 20 + t] * 256 + d];
    __nv_bfloat16 h, l; split_bf(v, h, l);
    g_Xhi[idx] = h; g_Xlo[idx] = l;
}

__global__ void gather_word_k(const int* __restrict__ word_src, const float* __restrict__ tab) {
    int idx = blockIdx.x * 256 + threadIdx.x;  // 8192*256 exact
    int n = idx >> 8, j = idx & 255;
    __nv_bfloat16 h, l; split_bf(tab[(size_t)word_src[n] * 256 + j], h, l);
    g_featshi[(size_t)n * 512 + 256 + j] = h;
    g_featslo[(size_t)n * 512 + 256 + j] = l;
}

// ---------------- bf16 mma.sync GEMM: C(128,128 tiles) = A * B^T, 3-segment split ----
// MODE: 0 = fp32 C + bias (xg), 1 = conv (bf16 cat + bcomb + pe), 2 = attn (tanh.ua reduce),
//       3 = w1 (bf16 feats, no bias)
template<int MODE>
__global__ void __launch_bounds__(256, 2) mma_gemm_k(
    const __nv_bfloat16* __restrict__ Ahi, const __nv_bfloat16* __restrict__ Alo,
    const __nv_bfloat16* __restrict__ Bhi, const __nv_bfloat16* __restrict__ Blo,
    int K,
    float* __restrict__ Cf, const float* __restrict__ bias, int ldc,
    const float* __restrict__ ba, const float* __restrict__ ua)
{
    extern __shared__ char smem[];
    uint32_t sb = smem_u32(smem);
    int tid = threadIdx.x, wid = tid >> 5, lane = tid & 31;
    int wm = wid & 1, wn = wid >> 1;
    int g = lane >> 2, t4 = lane & 3;
    int m0 = (MODE == 2) ? blockIdx.x * 128 : blockIdx.y * 128;
    int n0 = (MODE == 2) ? 0 : blockIdx.x * 128;

    int* winb = (int*)(smem + SM_WIN);
    if (MODE == 1 && tid < 128) {
        int m = m0 + tid;
        winb[tid] = (m / 20) * 5632 + (m % 20) * 256;
    }
    __syncthreads();

    int lr = tid >> 2;          // 0..63
    int lc = tid & 3;           // chunk
    const int nChunk = K >> 5;  // k-tiles of 32
    const int NIT = 3 * nChunk;
    const int npass = (MODE == 2) ? 4 : 1;

    float rs[4][2];
#pragma unroll
    for (int mi = 0; mi < 4; mi++) { rs[mi][0] = 0.f; rs[mi][1] = 0.f; }

    for (int ps = 0; ps < npass; ps++) {
        int bRow0 = (MODE == 2) ? ps * 128 : n0;

        float acc[4][4][4];
#pragma unroll
        for (int mi = 0; mi < 4; mi++)
#pragma unroll
            for (int ni = 0; ni < 4; ni++)
#pragma unroll
                for (int j = 0; j < 4; j++) acc[mi][ni][j] = 0.f;

#define ISSUE_TILE(IT, BUF)                                                          \
        {                                                                            \
            int seg_ = (IT) / nChunk;                                                \
            int kl_ = ((IT) - seg_ * nChunk) * 32;                                   \
            const __nv_bfloat16* As_ = (seg_ == 1) ? Alo : Ahi;                      \
            const __nv_bfloat16* Bs_ = (seg_ == 2) ? Blo : Bhi;                      \
            uint32_t ab_ = sb + (BUF) * BUFB;                                        \
            uint32_t bb_ = ab_ + TILEB;                                              \
            size_t ga0, ga1;                                                         \
            if (MODE == 1) {                                                         \
                ga0 = (size_t)winb[lr] + kl_ + lc * 8;                               \
                ga1 = (size_t)winb[lr + 64] + kl_ + lc * 8;                          \
            } else {                                                                 \
                ga0 = (size_t)(m0 + lr) * K + kl_ + lc * 8;                          \
                ga1 = (size_t)(m0 + lr + 64) * K + kl_ + lc * 8;                     \
            }                                                                        \
            CP_ASYNC16(ab_ + lr * ROWB + lc * 16, As_ + ga0);                        \
            CP_ASYNC16(ab_ + (lr + 64) * ROWB + lc * 16, As_ + ga1);                 \
            size_t gb0 = (size_t)(bRow0 + lr) * K + kl_ + lc * 8;                    \
            size_t gb1 = (size_t)(bRow0 + lr + 64) * K + kl_ + lc * 8;               \
            CP_ASYNC16(bb_ + lr * ROWB + lc * 16, Bs_ + gb0);                        \
            CP_ASYNC16(bb_ + (lr + 64) * ROWB + lc * 16, Bs_ + gb1);                 \
            CP_COMMIT();                                                             \
        }

        ISSUE_TILE(0, 0)
        for (int it = 0; it < NIT; it++) {
            if (it + 1 < NIT) { ISSUE_TILE(it + 1, (it + 1) & 1) CP_WAIT1(); }
            else CP_WAIT0();
            __syncthreads();
            {
                uint32_t ab = sb + (it & 1) * BUFB;
                uint32_t bb = ab + TILEB;
                uint32_t a_lane = ab + (uint32_t)(wm * 64 + (lane & 15)) * ROWB + (uint32_t)(lane >> 4) * 16;
                uint32_t b_lane = bb + (uint32_t)(wn * 32 + (lane & 7)) * ROWB + (uint32_t)((lane >> 3) & 1) * 16;
#pragma unroll
                for (int s = 0; s < 2; s++) {
                    uint32_t af[4][4], bf[4][2];
#pragma unroll
                    for (int mi = 0; mi < 4; mi++)
                        ldsm_x4(af[mi], a_lane + (uint32_t)(mi * 16 * ROWB) + (uint32_t)(s * 32));
#pragma unroll
                    for (int ni = 0; ni < 4; ni++)
                        ldsm_x2(bf[ni], b_lane + (uint32_t)(ni * 8 * ROWB) + (uint32_t)(s * 32));
#pragma unroll
                    for (int mi = 0; mi < 4; mi++)
#pragma unroll
                        for (int ni = 0; ni < 4; ni++)
                            mma_bf16(acc[mi][ni], af[mi], bf[ni]);
                }
            }
            __syncthreads();
        }
#undef ISSUE_TILE

        if (MODE == 2) {
#pragma unroll
            for (int mi = 0; mi < 4; mi++)
#pragma unroll
                for (int ni = 0; ni < 4; ni++)
#pragma unroll
                    for (int cj = 0; cj < 4; cj++) {
                        int col = ps * 128 + wn * 32 + ni * 8 + t4 * 2 + (cj & 1);
                        rs[mi][cj >> 1] += tanh_f(acc[mi][ni][cj] + __ldg(ba + col)) * __ldg(ua + col);
                    }
        } else {
#pragma unroll
            for (int mi = 0; mi < 4; mi++) {
#pragma unroll
                for (int half = 0; half < 2; half++) {
                    int m = m0 + wm * 64 + mi * 16 + g + half * 8;
#pragma unroll
                    for (int ni = 0; ni < 4; ni++) {
                        int n = n0 + wn * 32 + ni * 8 + t4 * 2;
                        float v0 = acc[mi][ni][half * 2 + 0];
                        float v1 = acc[mi][ni][half * 2 + 1];
                        if (MODE == 0) {
                            Cf[(size_t)m * ldc + n]     = v0 + __ldg(bias + n);
                            Cf[(size_t)m * ldc + n + 1] = v1 + __ldg(bias + n + 1);
                        } else if (MODE == 1) {
                            int t = m % 20;
                            float w0 = v0 + g_bcomb[n]     + g_pe[t * 256 + (n & 255)];
                            float w1 = v1 + g_bcomb[n + 1] + g_pe[t * 256 + ((n + 1) & 255)];
                            __nv_bfloat16 h, l;
                            split_bf(w0, h, l);
                            g_cathi[(size_t)m * 512 + n] = h; g_catlo[(size_t)m * 512 + n] = l;
                            split_bf(w1, h, l);
                            g_cathi[(size_t)m * 512 + n + 1] = h; g_catlo[(size_t)m * 512 + n + 1] = l;
                        } else {  // MODE 3
                            __nv_bfloat16 h, l;
                            split_bf(v0, h, l);
                            g_featshi[(size_t)m * 512 + n] = h; g_featslo[(size_t)m * 512 + n] = l;
                            split_bf(v1, h, l);
                            g_featshi[(size_t)m * 512 + n + 1] = h; g_featslo[(size_t)m * 512 + n + 1] = l;
                        }
                    }
                }
            }
        }
    }

    if (MODE == 2) {
        float* red = (float*)(smem + SM_RED);
#pragma unroll
        for (int mi = 0; mi < 4; mi++)
#pragma unroll
            for (int h = 0; h < 2; h++) {
                float v = rs[mi][h];
                v += __shfl_xor_sync(0xffffffffu, v, 1);
                v += __shfl_xor_sync(0xffffffffu, v, 2);
                if (t4 == 0) {
                    int r = wm * 64 + mi * 16 + g + h * 8;
                    red[r * 4 + wn] = v;
                }
            }
        __syncthreads();
        if (tid < 128) {
            float s = red[tid * 4] + red[tid * 4 + 1] + red[tid * 4 + 2] + red[tid * 4 + 3];
            g_score[m0 + tid] = s;
        }
    }
}

// ---------------- softmax over 20 chars + weighted pool (bf16-pair input) -------------
__global__ void softmax_wemb_k() {
    __shared__ float a[20];
    int n = blockIdx.x, tid = threadIdx.x;
    if (tid == 0) {
        float sc[20]; float mx = -1e30f;
        for (int c = 0; c < 20; c++) { sc[c] = g_score[n * 20 + c]; mx = fmaxf(mx, sc[c]); }
        float sum = 0.f;
        for (int c = 0; c < 20; c++) { sc[c] = expf(sc[c] - mx); sum += sc[c]; }
        float inv = 1.f / sum;
        for (int c = 0; c < 20; c++) a[c] = sc[c] * inv;
    }
    __syncthreads();
    size_t base = (size_t)n * 20 * 512;
    for (int d = tid; d < 512; d += 128) {
        float s = 0.f;
#pragma unroll
        for (int c = 0; c < 20; c++) {
            size_t i = base + (size_t)c * 512 + d;
            s += (__bfloat162float(g_cathi[i]) + __bfloat162float(g_catlo[i])) * a[c];
        }
        __nv_bfloat16 h, l; split_bf(s, h, l);
        g_wembhi[(size_t)n * 512 + d] = h;
        g_wemblo[(size_t)n * 512 + d] = l;
    }
}

// ---------------- persistent BiLSTM layer (packed f32x2 gates) ----------------
#define HS_STRIDE 516   // floats, conflict-free float4 rows
#define W2_STRIDE 514   // ulonglong pairs, conflict-free 16B rows
#define LSTM_SMEM (16*W2_STRIDE*8 + 64*HS_STRIDE*4)   // 65792 + 132096 = 197888

__global__ void __launch_bounds__(256) lstm_layer_k(const float* __restrict__ whh, int which) {
    extern __shared__ char shraw[];
    unsigned long long* whh2 = (unsigned long long*)shraw;       // [16][514] (gp*8+ul rows)
    float* h_s = (float*)(shraw + 16 * W2_STRIDE * 8);           // [64][516]
    int tid = threadIdx.x;
    int bd = blockIdx.x;
    int dir = bd >> 6;
    int uc = bd & 63;
    int u0 = uc * 8;
    const float* whhd = whh + (size_t)dir * 2048 * 512;
    // stage whh as packed gate pairs: row gp*8+ul, element k = (w_{2gp}, w_{2gp+1})
    for (int idx = tid; idx < 16 * 512; idx += 256) {
        int row = idx >> 9, k = idx & 511;
        int gp = row >> 3, ul2 = row & 7;
        int u = u0 + ul2;
        float x = whhd[(size_t)((2 * gp) * 512 + u) * 512 + k];
        float y = whhd[(size_t)((2 * gp + 1) * 512 + u) * 512 + k];
        whh2[row * W2_STRIDE + k] = pack2(x, y);
    }
    int ul = tid & 7;
    int bp = tid >> 3;
    float c0 = 0.f, c1 = 0.f;
    const int u = u0 + ul;
    const unsigned long long* wif = whh2 + ul * W2_STRIDE;        // (i,f) pairs
    const unsigned long long* wgo = whh2 + (8 + ul) * W2_STRIDE;  // (g,o) pairs
    const float* hap = h_s + bp * HS_STRIDE;
    const float* hbp = h_s + (bp + 32) * HS_STRIDE;

    for (int s = 0; s < 128; s++) {
        const float* hp = g_hbuf + ((size_t)((s & 1) * 2 + dir)) * 64 * 512;
        for (int idx = tid; idx < 64 * 512; idx += 256) {
            int b = idx >> 9, k = idx & 511;
            h_s[b * HS_STRIDE + k] = __ldcg(hp + idx);
        }
        __syncthreads();

        unsigned long long aif0 = 0, ago0 = 0, aif1 = 0, ago1 = 0;
#pragma unroll 4
        for (int k = 0; k < 512; k += 4) {
            ulonglong2 wa = *(const ulonglong2*)(wif + k);
            ulonglong2 wb = *(const ulonglong2*)(wif + k + 2);
            ulonglong2 ga = *(const ulonglong2*)(wgo + k);
            ulonglong2 gb = *(const ulonglong2*)(wgo + k + 2);
            float4 ha4 = *(const float4*)(hap + k);
            float4 hb4 = *(const float4*)(hbp + k);
            unsigned long long h0 = pack2(ha4.x, ha4.x), h1 = pack2(ha4.y, ha4.y);
            unsigned long long h2 = pack2(ha4.z, ha4.z), h3 = pack2(ha4.w, ha4.w);
            unsigned long long j0 = pack2(hb4.x, hb4.x), j1 = pack2(hb4.y, hb4.y);
            unsigned long long j2 = pack2(hb4.z, hb4.z), j3 = pack2(hb4.w, hb4.w);
            fma2(aif0, wa.x, h0); fma2(ago0, ga.x, h0);
            fma2(aif1, wa.x, j0); fma2(ago1, ga.x, j0);
            fma2(aif0, wa.y, h1); fma2(ago0, ga.y, h1);
            fma2(aif1, wa.y, j1); fma2(ago1, ga.y, j1);
            fma2(aif0, wb.x, h2); fma2(ago0, gb.x, h2);
            fma2(aif1, wb.x, j2); fma2(ago1, gb.x, j2);
            fma2(aif0, wb.y, h3); fma2(ago0, gb.y, h3);
            fma2(aif1, wb.y, j3); fma2(ago1, gb.y, j3);
        }
        int t = dir ? (127 - s) : s;
        size_t nbuf = ((size_t)(((s & 1) ^ 1) * 2 + dir)) * 64 * 512;
        {
            float ai, af, ag, ao;
            unpack2(aif0, ai, af); unpack2(ago0, ag, ao);
            size_t base = ((size_t)(bp * 128 + t)) * 4096 + (size_t)dir * 2048;
            float gi = ai + g_xg[base + u];
            float gf = af + g_xg[base + 512 + u];
            float gg = ag + g_xg[base + 1024 + u];
            float go = ao + g_xg[base + 1536 + u];
            c0 = sigf(gf) * c0 + sigf(gi) * tanh_f(gg);
            float h = sigf(go) * tanh_f(c0);
            g_hbuf[nbuf + bp * 512 + u] = h;
            size_t orow = ((size_t)(bp * 128 + t)) * 1024 + dir * 512 + u;
            if (which) g_h1[orow] = h;
            else { __nv_bfloat16 hh, ll; split_bf(h, hh, ll); g_h0hi[orow] = hh; g_h0lo[orow] = ll; }
        }
        {
            int b = bp + 32;
            float ai, af, ag, ao;
            unpack2(aif1, ai, af); unpack2(ago1, ag, ao);
            size_t base = ((size_t)(b * 128 + t)) * 4096 + (size_t)dir * 2048;
            float gi = ai + g_xg[base + u];
            float gf = af + g_xg[base + 512 + u];
            float gg = ag + g_xg[base + 1024 + u];
            float go = ao + g_xg[base + 1536 + u];
            c1 = sigf(gf) * c1 + sigf(gi) * tanh_f(gg);
            float h = sigf(go) * tanh_f(c1);
            g_hbuf[nbuf + b * 512 + u] = h;
            size_t orow = ((size_t)(b * 128 + t)) * 1024 + dir * 512 + u;
            if (which) g_h1[orow] = h;
            else { __nv_bfloat16 hh, ll; split_bf(h, hh, ll); g_h0hi[orow] = hh; g_h0lo[orow] = ll; }
        }
        __threadfence();
        __syncthreads();
        if (tid == 0) {
            atomicAdd(&g_bar[0], 1u);
            unsigned target = (unsigned)NBLK * (unsigned)(s + 1);
            while (atomicAdd(&g_bar[0], 0u) < target) { }
        }
        __syncthreads();
    }
}

__global__ void lstm_reset_k() {
    int idx = blockIdx.x * 256 + threadIdx.x;  // 131072 exact
    g_hbuf[idx] = 0.f;
    if (idx < 16) g_bar[idx] = 0u;
}

// ---------------- mean pool + output projection ----------------
__global__ void pool_out_k(const float* __restrict__ Wout, float* __restrict__ out) {
    __shared__ float pooled[1024];
    __shared__ float red[256 * 4];
    int b = blockIdx.x, tid = threadIdx.x;
    for (int u = tid; u < 1024; u += 256) {
        float s = 0.f;
        for (int t = 0; t < 128; t++) s += g_h1[((size_t)(b * 128 + t)) * 1024 + u];
        pooled[u] = s * (1.f / 128.f);
    }
    __syncthreads();
    float loc[4] = {0.f, 0.f, 0.f, 0.f};
    for (int u = tid; u < 1024; u += 256) {
        float p = pooled[u];
#pragma unroll
        for (int o = 0; o < 4; o++) loc[o] += p * Wout[u * 4 + o];
    }
#pragma unroll
    for (int o = 0; o < 4; o++) red[tid * 4 + o] = loc[o];
    __syncthreads();
    if (tid < 4) {
        float s = 0.f;
        for (int i = 0; i < 256; i++) s += red[i * 4 + tid];
        out[b * 4 + tid] = s;
    }
}

// ---------------- launch ----------------
extern "C" void kernel_launch(void* const* d_in, const int* in_sizes, int n_in,
                              void* d_out, int out_size) {
    const int*   src        = (const int*)  d_in[0];
    const int*   word_src   = (const int*)  d_in[1];
    const float* char_table = (const float*)d_in[2];
    const float* word_table = (const float*)d_in[3];
    const float* w_bi  = (const float*)d_in[4];
    const float* b_bi  = (const float*)d_in[5];
    const float* w_tri = (const float*)d_in[6];
    const float* b_tri = (const float*)d_in[7];
    const float* Wa    = (const float*)d_in[8];
    const float* ba    = (const float*)d_in[9];
    const float* ua    = (const float*)d_in[10];
    const float* W1    = (const float*)d_in[11];
    const float* wih0  = (const float*)d_in[12];
    const float* whh0  = (const float*)d_in[13];
    const float* b0    = (const float*)d_in[14];
    const float* wih1  = (const float*)d_in[15];
    const float* whh1  = (const float*)d_in[16];
    const float* b1    = (const float*)d_in[17];
    const float* Wout  = (const float*)d_in[18];
    float* out = (float*)d_out;
    (void)in_sizes; (void)n_in; (void)out_size;

    cudaFuncSetAttribute(lstm_layer_k, cudaFuncAttributeMaxDynamicSharedMemorySize, LSTM_SMEM);
    cudaFuncSetAttribute(mma_gemm_k<0>, cudaFuncAttributeMaxDynamicSharedMemorySize, SMEM_DYN);
    cudaFuncSetAttribute(mma_gemm_k<1>, cudaFuncAttributeMaxDynamicSharedMemorySize, SMEM_DYN);
    cudaFuncSetAttribute(mma_gemm_k<2>, cudaFuncAttributeMaxDynamicSharedMemorySize, SMEM_DYN);
    cudaFuncSetAttribute(mma_gemm_k<3>, cudaFuncAttributeMaxDynamicSharedMemorySize, SMEM_DYN);

    __nv_bfloat16 *pXhi, *pXlo, *pCathi, *pCatlo, *pWembhi, *pWemblo, *pFhi, *pFlo,
                  *pH0hi, *pH0lo, *pWchi, *pWclo, *pWahi, *pWalo, *pW1hi, *pW1lo,
                  *pWi0hi, *pWi0lo, *pWi1hi, *pWi1lo;
    float *pXg;
    cudaGetSymbolAddress((void**)&pXhi, g_Xhi);     cudaGetSymbolAddress((void**)&pXlo, g_Xlo);
    cudaGetSymbolAddress((void**)&pCathi, g_cathi); cudaGetSymbolAddress((void**)&pCatlo, g_catlo);
    cudaGetSymbolAddress((void**)&pWembhi, g_wembhi); cudaGetSymbolAddress((void**)&pWemblo, g_wemblo);
    cudaGetSymbolAddress((void**)&pFhi, g_featshi); cudaGetSymbolAddress((void**)&pFlo, g_featslo);
    cudaGetSymbolAddress((void**)&pH0hi, g_h0hi);   cudaGetSymbolAddress((void**)&pH0lo, g_h0lo);
    cudaGetSymbolAddress((void**)&pWchi, g_Wcombhi); cudaGetSymbolAddress((void**)&pWclo, g_Wcomblo);
    cudaGetSymbolAddress((void**)&pWahi, g_WaThi);  cudaGetSymbolAddress((void**)&pWalo, g_WaTlo);
    cudaGetSymbolAddress((void**)&pW1hi, g_W1Thi);  cudaGetSymbolAddress((void**)&pW1lo, g_W1Tlo);
    cudaGetSymbolAddress((void**)&pWi0hi, g_wih0hi); cudaGetSymbolAddress((void**)&pWi0lo, g_wih0lo);
    cudaGetSymbolAddress((void**)&pWi1hi, g_wih1hi); cudaGetSymbolAddress((void**)&pWi1lo, g_wih1lo);
    cudaGetSymbolAddress((void**)&pXg, g_xg);

    gather_x_k<<<8192 * 22, 256>>>(src, char_table);
    prep_wcomb_k<<<1536, 256>>>(w_bi, w_tri, b_bi, b_tri);
    prep_pe_k<<<20, 256>>>();
    { dim3 gr(4, 1280); mma_gemm_k<1><<<gr, 256, SMEM_DYN>>>(pXhi, pXlo, pWchi, pWclo,
        768, nullptr, nullptr, 0, nullptr, nullptr); }

    prep_wat_k<<<1024, 256>>>(Wa);
    mma_gemm_k<2><<<1280, 256, SMEM_DYN>>>(pCathi, pCatlo, pWahi, pWalo,
        512, nullptr, nullptr, 0, ba, ua);
    softmax_wemb_k<<<8192, 128>>>();

    prep_w1t_k<<<512, 256>>>(W1);
    { dim3 gr(2, 64); mma_gemm_k<3><<<gr, 256, SMEM_DYN>>>(pWembhi, pWemblo, pW1hi, pW1lo,
        512, nullptr, nullptr, 0, nullptr, nullptr); }
    gather_word_k<<<8192, 256>>>(word_src, word_table);

    // layer 0
    split2_k<<<8192, 256>>>(wih0, pWi0hi, pWi0lo, 4096 * 512);
    { dim3 gr(32, 64); mma_gemm_k<0><<<gr, 256, SMEM_DYN>>>(pFhi, pFlo, pWi0hi, pWi0lo,
        512, pXg, b0, 4096, nullptr, nullptr); }
    lstm_reset_k<<<512, 256>>>();
    lstm_layer_k<<<NBLK, 256, LSTM_SMEM>>>(whh0, 0);

    // layer 1
    split2_k<<<16384, 256>>>(wih1, pWi1hi, pWi1lo, 4096 * 1024);
    { dim3 gr(32, 64); mma_gemm_k<0><<<gr, 256, SMEM_DYN>>>(pH0hi, pH0lo, pWi1hi, pWi1lo,
        1024, pXg, b1, 4096, nullptr, nullptr); }
    lstm_reset_k<<<512, 256>>>();
    lstm_layer_k<<<NBLK, 256, LSTM_SMEM>>>(whh1, 1);

    pool_out_k<<<64, 256>>>(Wout, out);
}

// round 13
// speedup vs baseline: 1.9265x; 1.0320x over previous
#include <cuda_runtime.h>
#include <cuda_bf16.h>
#include <math.h>
#include <stddef.h>
#include <stdint.h>

// ---------------- problem constants ----------------
#define BB   64
#define WW   128
#define CC   20
#define DD   256
#define NTOK (BB*WW)          // 8192
#define NPOS (NTOK*CC)        // 163840
#define NBLK 128

// ---------------- device scratch ----------------
__device__ __nv_bfloat16 g_Xhi[(size_t)NTOK*22*DD];
__device__ __nv_bfloat16 g_Xlo[(size_t)NTOK*22*DD];
__device__ __nv_bfloat16 g_cathi[(size_t)NPOS*512];
__device__ __nv_bfloat16 g_catlo[(size_t)NPOS*512];
__device__ __nv_bfloat16 g_wembhi[(size_t)NTOK*512];
__device__ __nv_bfloat16 g_wemblo[(size_t)NTOK*512];
__device__ __nv_bfloat16 g_featshi[(size_t)NTOK*512];
__device__ __nv_bfloat16 g_featslo[(size_t)NTOK*512];
__device__ __nv_bfloat16 g_h0hi[(size_t)NTOK*1024];
__device__ __nv_bfloat16 g_h0lo[(size_t)NTOK*1024];
__device__ __nv_bfloat16 g_Wcombhi[512*768];
__device__ __nv_bfloat16 g_Wcomblo[512*768];
__device__ __nv_bfloat16 g_WaThi[512*512];
__device__ __nv_bfloat16 g_WaTlo[512*512];
__device__ __nv_bfloat16 g_W1Thi[256*512];
__device__ __nv_bfloat16 g_W1Tlo[256*512];
__device__ __nv_bfloat16 g_wih0hi[4096*512];
__device__ __nv_bfloat16 g_wih0lo[4096*512];
__device__ __nv_bfloat16 g_wih1hi[(size_t)4096*1024];
__device__ __nv_bfloat16 g_wih1lo[(size_t)4096*1024];
__device__ float g_xg[(size_t)NTOK*4096];
__device__ float g_h1[(size_t)NTOK*1024];
__device__ float g_hbuf[2*2*64*512];
__device__ float g_score[NPOS];
__device__ float g_pe[20*256];
__device__ float g_bcomb[512];
__device__ unsigned int g_bar[16];

// ---------------- math helpers ----------------
__device__ __forceinline__ float sigf(float x) { return 1.f / (1.f + expf(-x)); }
__device__ __forceinline__ float tanh_f(float x) {
    float e = expf(-2.f * fabsf(x));
    float r = (1.f - e) / (1.f + e);
    return x >= 0.f ? r : -r;
}
__device__ __forceinline__ void split_bf(float v, __nv_bfloat16& hi, __nv_bfloat16& lo) {
    hi = __float2bfloat16(v);
    lo = __float2bfloat16(v - __bfloat162float(hi));
}

// ---------------- packed f32x2 helpers (B300 FFMA2) ----------------
__device__ __forceinline__ void fma2(unsigned long long& c, unsigned long long a, unsigned long long b) {
    asm("fma.rn.f32x2 %0, %1, %2, %0;" : "+l"(c) : "l"(a), "l"(b));
}
__device__ __forceinline__ unsigned long long pack2(float x, float y) {
    unsigned long long r; asm("mov.b64 %0, {%1, %2};" : "=l"(r) : "f"(x), "f"(y)); return r;
}
__device__ __forceinline__ void unpack2(unsigned long long v, float& x, float& y) {
    asm("mov.b64 {%0, %1}, %2;" : "=f"(x), "=f"(y) : "l"(v));
}

// ---------------- mma.sync bf16 helpers ----------------
__device__ __forceinline__ uint32_t smem_u32(const void* p) {
    uint32_t a;
    asm("{ .reg .u64 t; cvta.to.shared.u64 t, %1; cvt.u32.u64 %0, t; }" : "=r"(a) : "l"(p));
    return a;
}
__device__ __forceinline__ void ldsm_x4(uint32_t* r, uint32_t addr) {
    asm volatile("ldmatrix.sync.aligned.m8n8.x4.shared.b16 {%0,%1,%2,%3}, [%4];"
        : "=r"(r[0]), "=r"(r[1]), "=r"(r[2]), "=r"(r[3]) : "r"(addr));
}
__device__ __forceinline__ void ldsm_x2(uint32_t* r, uint32_t addr) {
    asm volatile("ldmatrix.sync.aligned.m8n8.x2.shared.b16 {%0,%1}, [%2];"
        : "=r"(r[0]), "=r"(r[1]) : "r"(addr));
}
__device__ __forceinline__ void mma_bf16(float* c, const uint32_t* a, const uint32_t* b) {
    asm volatile("mma.sync.aligned.m16n8k16.row.col.f32.bf16.bf16.f32 "
        "{%0,%1,%2,%3}, {%4,%5,%6,%7}, {%8,%9}, {%0,%1,%2,%3};"
        : "+f"(c[0]), "+f"(c[1]), "+f"(c[2]), "+f"(c[3])
        : "r"(a[0]), "r"(a[1]), "r"(a[2]), "r"(a[3]), "r"(b[0]), "r"(b[1]));
}
#define CP_ASYNC16(dst, src) \
    asm volatile("cp.async.cg.shared.global [%0], [%1], 16;" :: "r"(dst), "l"(src))
#define CP_COMMIT() asm volatile("cp.async.commit_group;" ::: "memory")
#define CP_WAIT1()  asm volatile("cp.async.wait_group 1;" ::: "memory")
#define CP_WAIT0()  asm volatile("cp.async.wait_group 0;" ::: "memory")

// smem layout: 80B-padded rows (conflict-free ldmatrix), TRIPLE-buffered A+B
#define ROWB   80
#define TILEB  (128*ROWB)          // 10240
#define BUFB   (2*TILEB)           // 20480 per buffer (A then B)
#define SM_RED (3*BUFB)            // 61440
#define SM_WIN (SM_RED + 2048)     // 63488
#define SMEM_DYN (SM_WIN + 512)    // 64000

// ---------------- prep kernels ----------------
__global__ void prep_pe_k() {
    int idx = blockIdx.x * 256 + threadIdx.x;
    if (idx >= 20 * 256) return;
    int t = idx >> 8, j = idx & 255;
    int m2 = j & ~1;
    float div = expf(-(float)m2 * (logf(10000.f) / 256.f));
    float ang = (float)t * div;
    g_pe[idx] = (j & 1) ? cosf(ang) : sinf(ang);
}

__global__ void prep_wcomb_k(const float* __restrict__ wbi, const float* __restrict__ wtri,
                             const float* __restrict__ bbi, const float* __restrict__ btri) {
    int idx = blockIdx.x * 256 + threadIdx.x;  // 512*768 exact
    int o = idx / 768, r = idx % 768;
    int kk = r >> 8, i = r & 255;
    float v;
    if (o < 256) v = (kk < 2) ? wbi[(o * 256 + i) * 2 + kk] : 0.f;
    else         v = wtri[((o - 256) * 256 + i) * 3 + kk];
    __nv_bfloat16 h, l; split_bf(v, h, l);
    g_Wcombhi[idx] = h; g_Wcomblo[idx] = l;
    if (idx < 512) g_bcomb[idx] = (idx < 256) ? bbi[idx] : btri[idx - 256];
}

__global__ void prep_wat_k(const float* __restrict__ Wa) {
    int idx = blockIdx.x * 256 + threadIdx.x;  // 512*512 exact
    int e = idx >> 9, d = idx & 511;
    __nv_bfloat16 h, l; split_bf(Wa[d * 512 + e], h, l);
    g_WaThi[idx] = h; g_WaTlo[idx] = l;
}

__global__ void prep_w1t_k(const float* __restrict__ W1) {
    int idx = blockIdx.x * 256 + threadIdx.x;  // 256*512 exact
    int j = idx >> 9, d = idx & 511;
    __nv_bfloat16 h, l; split_bf(W1[d * 256 + j], h, l);
    g_W1Thi[idx] = h; g_W1Tlo[idx] = l;
}

__global__ void split2_k(const float* __restrict__ in, __nv_bfloat16* __restrict__ hi,
                         __nv_bfloat16* __restrict__ lo, int n) {
    int i = blockIdx.x * 256 + threadIdx.x;
    if (i >= n) return;
    __nv_bfloat16 h, l; split_bf(in[i], h, l);
    hi[i] = h; lo[i] = l;
}

__global__ void gather_x_k(const int* __restrict__ src, const float* __restrict__ tab) {
    size_t idx = (size_t)blockIdx.x * 256 + threadIdx.x;  // 8192*22*256 exact
    int d = (int)(idx & 255);
    size_t row = idx >> 8;
    int t = (int)(row % 22);
    size_t n = row / 22;
    float v = 0.f;
    if (t < 20) v = tab[(size_t)src[n * 20 + t] * 256 + d];
    __nv_bfloat16 h, l; split_bf(v, h, l);
    g_Xhi[idx] = h; g_Xlo[idx] = l;
}

__global__ void gather_word_k(const int* __restrict__ word_src, const float* __restrict__ tab) {
    int idx = blockIdx.x * 256 + threadIdx.x;  // 8192*256 exact
    int n = idx >> 8, j = idx & 255;
    __nv_bfloat16 h, l; split_bf(tab[(size_t)word_src[n] * 256 + j], h, l);
    g_featshi[(size_t)n * 512 + 256 + j] = h;
    g_featslo[(size_t)n * 512 + 256 + j] = l;
}

// ---------------- bf16 mma.sync GEMM, 3-stage cp.async pipeline ----------------
// MODE: 0 = fp32 C + bias (xg), 1 = conv (bf16 cat + bcomb + pe), 2 = attn (tanh.ua reduce),
//       3 = w1 (bf16 feats, no bias)
template<int MODE>
__global__ void __launch_bounds__(256, 2) mma_gemm_k(
    const __nv_bfloat16* __restrict__ Ahi, const __nv_bfloat16* __restrict__ Alo,
    const __nv_bfloat16* __restrict__ Bhi, const __nv_bfloat16* __restrict__ Blo,
    int K,
    float* __restrict__ Cf, const float* __restrict__ bias, int ldc,
    const float* __restrict__ ba, const float* __restrict__ ua)
{
    extern __shared__ char smem[];
    uint32_t sb = smem_u32(smem);
    int tid = threadIdx.x, wid = tid >> 5, lane = tid & 31;
    int wm = wid & 1, wn = wid >> 1;
    int g = lane >> 2, t4 = lane & 3;
    int m0 = (MODE == 2) ? blockIdx.x * 128 : blockIdx.y * 128;
    int n0 = (MODE == 2) ? 0 : blockIdx.x * 128;

    int* winb = (int*)(smem + SM_WIN);
    if (MODE == 1 && tid < 128) {
        int m = m0 + tid;
        winb[tid] = (m / 20) * 5632 + (m % 20) * 256;
    }
    __syncthreads();

    int lr = tid >> 2;          // 0..63
    int lc = tid & 3;           // chunk
    const int nChunk = K >> 5;  // k-tiles of 32
    const int NIT = 3 * nChunk;
    const int npass = (MODE == 2) ? 4 : 1;

    float rs[4][2];
#pragma unroll
    for (int mi = 0; mi < 4; mi++) { rs[mi][0] = 0.f; rs[mi][1] = 0.f; }

    for (int ps = 0; ps < npass; ps++) {
        int bRow0 = (MODE == 2) ? ps * 128 : n0;
        if (ps > 0) __syncthreads();   // all warps done reading buffers from previous pass

        float acc[4][4][4];
#pragma unroll
        for (int mi = 0; mi < 4; mi++)
#pragma unroll
            for (int ni = 0; ni < 4; ni++)
#pragma unroll
                for (int j = 0; j < 4; j++) acc[mi][ni][j] = 0.f;

#define ISSUE_TILE(IT, BUF)                                                          \
        {                                                                            \
            int seg_ = (IT) / nChunk;                                                \
            int kl_ = ((IT) - seg_ * nChunk) * 32;                                   \
            const __nv_bfloat16* As_ = (seg_ == 1) ? Alo : Ahi;                      \
            const __nv_bfloat16* Bs_ = (seg_ == 2) ? Blo : Bhi;                      \
            uint32_t ab_ = sb + (BUF) * BUFB;                                        \
            uint32_t bb_ = ab_ + TILEB;                                              \
            size_t ga0, ga1;                                                         \
            if (MODE == 1) {                                                         \
                ga0 = (size_t)winb[lr] + kl_ + lc * 8;                               \
                ga1 = (size_t)winb[lr + 64] + kl_ + lc * 8;                          \
            } else {                                                                 \
                ga0 = (size_t)(m0 + lr) * K + kl_ + lc * 8;                          \
                ga1 = (size_t)(m0 + lr + 64) * K + kl_ + lc * 8;                     \
            }                                                                        \
            CP_ASYNC16(ab_ + lr * ROWB + lc * 16, As_ + ga0);                        \
            CP_ASYNC16(ab_ + (lr + 64) * ROWB + lc * 16, As_ + ga1);                 \
            size_t gb0 = (size_t)(bRow0 + lr) * K + kl_ + lc * 8;                    \
            size_t gb1 = (size_t)(bRow0 + lr + 64) * K + kl_ + lc * 8;               \
            CP_ASYNC16(bb_ + lr * ROWB + lc * 16, Bs_ + gb0);                        \
            CP_ASYNC16(bb_ + (lr + 64) * ROWB + lc * 16, Bs_ + gb1);                 \
            CP_COMMIT();                                                             \
        }

        ISSUE_TILE(0, 0)
        ISSUE_TILE(1, 1)
        for (int it = 0; it < NIT; it++) {
            if (it < NIT - 1) CP_WAIT1(); else CP_WAIT0();
            __syncthreads();
            {
                int bufc = it % 3;
                uint32_t ab = sb + (uint32_t)bufc * BUFB;
                uint32_t bb = ab + TILEB;
                uint32_t a_lane = ab + (uint32_t)(wm * 64 + (lane & 15)) * ROWB + (uint32_t)(lane >> 4) * 16;
                uint32_t b_lane = bb + (uint32_t)(wn * 32 + (lane & 7)) * ROWB + (uint32_t)((lane >> 3) & 1) * 16;
#pragma unroll
                for (int s = 0; s < 2; s++) {
                    uint32_t af[4][4], bf[4][2];
#pragma unroll
                    for (int mi = 0; mi < 4; mi++)
                        ldsm_x4(af[mi], a_lane + (uint32_t)(mi * 16 * ROWB) + (uint32_t)(s * 32));
#pragma unroll
                    for (int ni = 0; ni < 4; ni++)
                        ldsm_x2(bf[ni], b_lane + (uint32_t)(ni * 8 * ROWB) + (uint32_t)(s * 32));
#pragma unroll
                    for (int mi = 0; mi < 4; mi++)
#pragma unroll
                        for (int ni = 0; ni < 4; ni++)
                            mma_bf16(acc[mi][ni], af[mi], bf[ni]);
                }
            }
            if (it + 2 < NIT) ISSUE_TILE(it + 2, (it + 2) % 3)
        }
#undef ISSUE_TILE

        if (MODE == 2) {
#pragma unroll
            for (int mi = 0; mi < 4; mi++)
#pragma unroll
                for (int ni = 0; ni < 4; ni++)
#pragma unroll
                    for (int cj = 0; cj < 4; cj++) {
                        int col = ps * 128 + wn * 32 + ni * 8 + t4 * 2 + (cj & 1);
                        rs[mi][cj >> 1] += tanh_f(acc[mi][ni][cj] + __ldg(ba + col)) * __ldg(ua + col);
                    }
        } else {
#pragma unroll
            for (int mi = 0; mi < 4; mi++) {
#pragma unroll
                for (int half = 0; half < 2; half++) {
                    int m = m0 + wm * 64 + mi * 16 + g + half * 8;
#pragma unroll
                    for (int ni = 0; ni < 4; ni++) {
                        int n = n0 + wn * 32 + ni * 8 + t4 * 2;
                        float v0 = acc[mi][ni][half * 2 + 0];
                        float v1 = acc[mi][ni][half * 2 + 1];
                        if (MODE == 0) {
                            Cf[(size_t)m * ldc + n]     = v0 + __ldg(bias + n);
                            Cf[(size_t)m * ldc + n + 1] = v1 + __ldg(bias + n + 1);
                        } else if (MODE == 1) {
                            int t = m % 20;
                            float w0 = v0 + g_bcomb[n]     + g_pe[t * 256 + (n & 255)];
                            float w1 = v1 + g_bcomb[n + 1] + g_pe[t * 256 + ((n + 1) & 255)];
                            __nv_bfloat16 h, l;
                            split_bf(w0, h, l);
                            g_cathi[(size_t)m * 512 + n] = h; g_catlo[(size_t)m * 512 + n] = l;
                            split_bf(w1, h, l);
                            g_cathi[(size_t)m * 512 + n + 1] = h; g_catlo[(size_t)m * 512 + n + 1] = l;
                        } else {  // MODE 3
                            __nv_bfloat16 h, l;
                            split_bf(v0, h, l);
                            g_featshi[(size_t)m * 512 + n] = h; g_featslo[(size_t)m * 512 + n] = l;
                            split_bf(v1, h, l);
                            g_featshi[(size_t)m * 512 + n + 1] = h; g_featslo[(size_t)m * 512 + n + 1] = l;
                        }
                    }
                }
            }
        }
    }

    if (MODE == 2) {
        float* red = (float*)(smem + SM_RED);
#pragma unroll
        for (int mi = 0; mi < 4; mi++)
#pragma unroll
            for (int h = 0; h < 2; h++) {
                float v = rs[mi][h];
                v += __shfl_xor_sync(0xffffffffu, v, 1);
                v += __shfl_xor_sync(0xffffffffu, v, 2);
                if (t4 == 0) {
                    int r = wm * 64 + mi * 16 + g + h * 8;
                    red[r * 4 + wn] = v;
                }
            }
        __syncthreads();
        if (tid < 128) {
            float s = red[tid * 4] + red[tid * 4 + 1] + red[tid * 4 + 2] + red[tid * 4 + 3];
            g_score[m0 + tid] = s;
        }
    }
}

// ---------------- softmax over 20 chars + weighted pool (bf16-pair input) -------------
__global__ void softmax_wemb_k() {
    __shared__ float a[20];
    int n = blockIdx.x, tid = threadIdx.x;
    if (tid == 0) {
        float sc[20]; float mx = -1e30f;
        for (int c = 0; c < 20; c++) { sc[c] = g_score[n * 20 + c]; mx = fmaxf(mx, sc[c]); }
        float sum = 0.f;
        for (int c = 0; c < 20; c++) { sc[c] = expf(sc[c] - mx); sum += sc[c]; }
        float inv = 1.f / sum;
        for (int c = 0; c < 20; c++) a[c] = sc[c] * inv;
    }
    __syncthreads();
    size_t base = (size_t)n * 20 * 512;
    for (int d = tid; d < 512; d += 128) {
        float s = 0.f;
#pragma unroll
        for (int c = 0; c < 20; c++) {
            size_t i = base + (size_t)c * 512 + d;
            s += (__bfloat162float(g_cathi[i]) + __bfloat162float(g_catlo[i])) * a[c];
        }
        __nv_bfloat16 h, l; split_bf(s, h, l);
        g_wembhi[(size_t)n * 512 + d] = h;
        g_wemblo[(size_t)n * 512 + d] = l;
    }
}

// ---------------- persistent BiLSTM layer (packed f32x2 gates) ----------------
#define HS_STRIDE 516   // floats, conflict-free float4 rows
#define W2_STRIDE 514   // ulonglong pairs, conflict-free 16B rows
#define LSTM_SMEM (16*W2_STRIDE*8 + 64*HS_STRIDE*4)   // 197888

__global__ void __launch_bounds__(256) lstm_layer_k(const float* __restrict__ whh, int which) {
    extern __shared__ char shraw[];
    unsigned long long* whh2 = (unsigned long long*)shraw;       // [16][514]
    float* h_s = (float*)(shraw + 16 * W2_STRIDE * 8);           // [64][516]
    int tid = threadIdx.x;
    int bd = blockIdx.x;
    int dir = bd >> 6;
    int uc = bd & 63;
    int u0 = uc * 8;
    const float* whhd = whh + (size_t)dir * 2048 * 512;
    for (int idx = tid; idx < 16 * 512; idx += 256) {
        int row = idx >> 9, k = idx & 511;
        int gp = row >> 3, ul2 = row & 7;
        int u = u0 + ul2;
        float x = whhd[(size_t)((2 * gp) * 512 + u) * 512 + k];
        float y = whhd[(size_t)((2 * gp + 1) * 512 + u) * 512 + k];
        whh2[row * W2_STRIDE + k] = pack2(x, y);
    }
    int ul = tid & 7;
    int bp = tid >> 3;
    float c0 = 0.f, c1 = 0.f;
    const int u = u0 + ul;
    const unsigned long long* wif = whh2 + ul * W2_STRIDE;
    const unsigned long long* wgo = whh2 + (8 + ul) * W2_STRIDE;
    const float* hap = h_s + bp * HS_STRIDE;
    const float* hbp = h_s + (bp + 32) * HS_STRIDE;

    for (int s = 0; s < 128; s++) {
        const float* hp = g_hbuf + ((size_t)((s & 1) * 2 + dir)) * 64 * 512;
        for (int idx = tid; idx < 64 * 512; idx += 256) {
            int b = idx >> 9, k = idx & 511;
            h_s[b * HS_STRIDE + k] = __ldcg(hp + idx);
        }
        __syncthreads();

        unsigned long long aif0 = 0, ago0 = 0, aif1 = 0, ago1 = 0;
#pragma unroll 4
        for (int k = 0; k < 512; k += 4) {
            ulonglong2 wa = *(const ulonglong2*)(wif + k);
            ulonglong2 wb = *(const ulonglong2*)(wif + k + 2);
            ulonglong2 ga = *(const ulonglong2*)(wgo + k);
            ulonglong2 gb = *(const ulonglong2*)(wgo + k + 2);
            float4 ha4 = *(const float4*)(hap + k);
            float4 hb4 = *(const float4*)(hbp + k);
            unsigned long long h0 = pack2(ha4.x, ha4.x), h1 = pack2(ha4.y, ha4.y);
            unsigned long long h2 = pack2(ha4.z, ha4.z), h3 = pack2(ha4.w, ha4.w);
            unsigned long long j0 = pack2(hb4.x, hb4.x), j1 = pack2(hb4.y, hb4.y);
            unsigned long long j2 = pack2(hb4.z, hb4.z), j3 = pack2(hb4.w, hb4.w);
            fma2(aif0, wa.x, h0); fma2(ago0, ga.x, h0);
            fma2(aif1, wa.x, j0); fma2(ago1, ga.x, j0);
            fma2(aif0, wa.y, h1); fma2(ago0, ga.y, h1);
            fma2(aif1, wa.y, j1); fma2(ago1, ga.y, j1);
            fma2(aif0, wb.x, h2); fma2(ago0, gb.x, h2);
            fma2(aif1, wb.x, j2); fma2(ago1, gb.x, j2);
            fma2(aif0, wb.y, h3); fma2(ago0, gb.y, h3);
            fma2(aif1, wb.y, j3); fma2(ago1, gb.y, j3);
        }
        int t = dir ? (127 - s) : s;
        size_t nbuf = ((size_t)(((s & 1) ^ 1) * 2 + dir)) * 64 * 512;
        {
            float ai, af, ag, ao;
            unpack2(aif0, ai, af); unpack2(ago0, ag, ao);
            size_t base = ((size_t)(bp * 128 + t)) * 4096 + (size_t)dir * 2048;
            float gi = ai + g_xg[base + u];
            float gf = af + g_xg[base + 512 + u];
            float gg = ag + g_xg[base + 1024 + u];
            float go = ao + g_xg[base + 1536 + u];
            c0 = sigf(gf) * c0 + sigf(gi) * tanh_f(gg);
            float h = sigf(go) * tanh_f(c0);
            g_hbuf[nbuf + bp * 512 + u] = h;
            size_t orow = ((size_t)(bp * 128 + t)) * 1024 + dir * 512 + u;
            if (which) g_h1[orow] = h;
            else { __nv_bfloat16 hh, ll; split_bf(h, hh, ll); g_h0hi[orow] = hh; g_h0lo[orow] = ll; }
        }
        {
            int b = bp + 32;
            float ai, af, ag, ao;
            unpack2(aif1, ai, af); unpack2(ago1, ag, ao);
            size_t base = ((size_t)(b * 128 + t)) * 4096 + (size_t)dir * 2048;
            float gi = ai + g_xg[base + u];
            float gf = af + g_xg[base + 512 + u];
            float gg = ag + g_xg[base + 1024 + u];
            float go = ao + g_xg[base + 1536 + u];
            c1 = sigf(gf) * c1 + sigf(gi) * tanh_f(gg);
            float h = sigf(go) * tanh_f(c1);
            g_hbuf[nbuf + b * 512 + u] = h;
            size_t orow = ((size_t)(b * 128 + t)) * 1024 + dir * 512 + u;
            if (which) g_h1[orow] = h;
            else { __nv_bfloat16 hh, ll; split_bf(h, hh, ll); g_h0hi[orow] = hh; g_h0lo[orow] = ll; }
        }
        __threadfence();
        __syncthreads();
        if (tid == 0) {
            atomicAdd(&g_bar[0], 1u);
            unsigned target = (unsigned)NBLK * (unsigned)(s + 1);
            while (atomicAdd(&g_bar[0], 0u) < target) { }
        }
        __syncthreads();
    }
}

__global__ void lstm_reset_k() {
    int idx = blockIdx.x * 256 + threadIdx.x;  // 131072 exact
    g_hbuf[idx] = 0.f;
    if (idx < 16) g_bar[idx] = 0u;
}

// ---------------- mean pool + output projection ----------------
__global__ void pool_out_k(const float* __restrict__ Wout, float* __restrict__ out) {
    __shared__ float pooled[1024];
    __shared__ float red[256 * 4];
    int b = blockIdx.x, tid = threadIdx.x;
    for (int u = tid; u < 1024; u += 256) {
        float s = 0.f;
        for (int t = 0; t < 128; t++) s += g_h1[((size_t)(b * 128 + t)) * 1024 + u];
        pooled[u] = s * (1.f / 128.f);
    }
    __syncthreads();
    float loc[4] = {0.f, 0.f, 0.f, 0.f};
    for (int u = tid; u < 1024; u += 256) {
        float p = pooled[u];
#pragma unroll
        for (int o = 0; o < 4; o++) loc[o] += p * Wout[u * 4 + o];
    }
#pragma unroll
    for (int o = 0; o < 4; o++) red[tid * 4 + o] = loc[o];
    __syncthreads();
    if (tid < 4) {
        float s = 0.f;
        for (int i = 0; i < 256; i++) s += red[i * 4 + tid];
        out[b * 4 + tid] = s;
    }
}

// ---------------- launch ----------------
extern "C" void kernel_launch(void* const* d_in, const int* in_sizes, int n_in,
                              void* d_out, int out_size) {
    const int*   src        = (const int*)  d_in[0];
    const int*   word_src   = (const int*)  d_in[1];
    const float* char_table = (const float*)d_in[2];
    const float* word_table = (const float*)d_in[3];
    const float* w_bi  = (const float*)d_in[4];
    const float* b_bi  = (const float*)d_in[5];
    const float* w_tri = (const float*)d_in[6];
    const float* b_tri = (const float*)d_in[7];
    const float* Wa    = (const float*)d_in[8];
    const float* ba    = (const float*)d_in[9];
    const float* ua    = (const float*)d_in[10];
    const float* W1    = (const float*)d_in[11];
    const float* wih0  = (const float*)d_in[12];
    const float* whh0  = (const float*)d_in[13];
    const float* b0    = (const float*)d_in[14];
    const float* wih1  = (const float*)d_in[15];
    const float* whh1  = (const float*)d_in[16];
    const float* b1    = (const float*)d_in[17];
    const float* Wout  = (const float*)d_in[18];
    float* out = (float*)d_out;
    (void)in_sizes; (void)n_in; (void)out_size;

    cudaFuncSetAttribute(lstm_layer_k, cudaFuncAttributeMaxDynamicSharedMemorySize, LSTM_SMEM);
    cudaFuncSetAttribute(mma_gemm_k<0>, cudaFuncAttributeMaxDynamicSharedMemorySize, SMEM_DYN);
    cudaFuncSetAttribute(mma_gemm_k<1>, cudaFuncAttributeMaxDynamicSharedMemorySize, SMEM_DYN);
    cudaFuncSetAttribute(mma_gemm_k<2>, cudaFuncAttributeMaxDynamicSharedMemorySize, SMEM_DYN);
    cudaFuncSetAttribute(mma_gemm_k<3>, cudaFuncAttributeMaxDynamicSharedMemorySize, SMEM_DYN);

    __nv_bfloat16 *pXhi, *pXlo, *pCathi, *pCatlo, *pWembhi, *pWemblo, *pFhi, *pFlo,
                  *pH0hi, *pH0lo, *pWchi, *pWclo, *pWahi, *pWalo, *pW1hi, *pW1lo,
                  *pWi0hi, *pWi0lo, *pWi1hi, *pWi1lo;
    float *pXg;
    cudaGetSymbolAddress((void**)&pXhi, g_Xhi);     cudaGetSymbolAddress((void**)&pXlo, g_Xlo);
    cudaGetSymbolAddress((void**)&pCathi, g_cathi); cudaGetSymbolAddress((void**)&pCatlo, g_catlo);
    cudaGetSymbolAddress((void**)&pWembhi, g_wembhi); cudaGetSymbolAddress((void**)&pWemblo, g_wemblo);
    cudaGetSymbolAddress((void**)&pFhi, g_featshi); cudaGetSymbolAddress((void**)&pFlo, g_featslo);
    cudaGetSymbolAddress((void**)&pH0hi, g_h0hi);   cudaGetSymbolAddress((void**)&pH0lo, g_h0lo);
    cudaGetSymbolAddress((void**)&pWchi, g_Wcombhi); cudaGetSymbolAddress((void**)&pWclo, g_Wcomblo);
    cudaGetSymbolAddress((void**)&pWahi, g_WaThi);  cudaGetSymbolAddress((void**)&pWalo, g_WaTlo);
    cudaGetSymbolAddress((void**)&pW1hi, g_W1Thi);  cudaGetSymbolAddress((void**)&pW1lo, g_W1Tlo);
    cudaGetSymbolAddress((void**)&pWi0hi, g_wih0hi); cudaGetSymbolAddress((void**)&pWi0lo, g_wih0lo);
    cudaGetSymbolAddress((void**)&pWi1hi, g_wih1hi); cudaGetSymbolAddress((void**)&pWi1lo, g_wih1lo);
    cudaGetSymbolAddress((void**)&pXg, g_xg);

    gather_x_k<<<8192 * 22, 256>>>(src, char_table);
    prep_wcomb_k<<<1536, 256>>>(w_bi, w_tri, b_bi, b_tri);
    prep_pe_k<<<20, 256>>>();
    { dim3 gr(4, 1280); mma_gemm_k<1><<<gr, 256, SMEM_DYN>>>(pXhi, pXlo, pWchi, pWclo,
        768, nullptr, nullptr, 0, nullptr, nullptr); }

    prep_wat_k<<<1024, 256>>>(Wa);
    mma_gemm_k<2><<<1280, 256, SMEM_DYN>>>(pCathi, pCatlo, pWahi, pWalo,
        512, nullptr, nullptr, 0, ba, ua);
    softmax_wemb_k<<<8192, 128>>>();

    prep_w1t_k<<<512, 256>>>(W1);
    { dim3 gr(2, 64); mma_gemm_k<3><<<gr, 256, SMEM_DYN>>>(pWembhi, pWemblo, pW1hi, pW1lo,
        512, nullptr, nullptr, 0, nullptr, nullptr); }
    gather_word_k<<<8192, 256>>>(word_src, word_table);

    // layer 0
    split2_k<<<8192, 256>>>(wih0, pWi0hi, pWi0lo, 4096 * 512);
    { dim3 gr(32, 64); mma_gemm_k<0><<<gr, 256, SMEM_DYN>>>(pFhi, pFlo, pWi0hi, pWi0lo,
        512, pXg, b0, 4096, nullptr, nullptr); }
    lstm_reset_k<<<512, 256>>>();
    lstm_layer_k<<<NBLK, 256, LSTM_SMEM>>>(whh0, 0);

    // layer 1
    split2_k<<<16384, 256>>>(wih1, pWi1hi, pWi1lo, 4096 * 1024);
    { dim3 gr(32, 64); mma_gemm_k<0><<<gr, 256, SMEM_DYN>>>(pH0hi, pH0lo, pWi1hi, pWi1lo,
        1024, pXg, b1, 4096, nullptr, nullptr); }
    lstm_reset_k<<<512, 256>>>();
    lstm_layer_k<<<NBLK, 256, LSTM_SMEM>>>(whh1, 1);

    pool_out_k<<<64, 256>>>(Wout, out);
}